// round 12
// baseline (speedup 1.0000x reference)
#include <cuda_runtime.h>
#include <cuda_bf16.h>
#include <math.h>
#include <cstdint>

#define BB 8
#define TT 2048
#define CC 1024
#define HH 64

// bf16 hi/lo tensors
__device__ __nv_bfloat16 g_xh[BB*TT*CC], g_xl[BB*TT*CC];   // x  [m][c]
__device__ __nv_bfloat16 g_qh[BB*TT*HH], g_ql[BB*TT*HH];   // q  [b][t][h] (x 0.125*log2e)
__device__ __nv_bfloat16 g_kh[BB*TT*HH], g_kl[BB*TT*HH];   // k  [b][t][h]
__device__ __nv_bfloat16 g_vth[BB*HH*TT], g_vtl[BB*HH*TT]; // v^T [b][h][t]
__device__ __nv_bfloat16 g_wt_hi[192*CC];                  // W^T [n][k], n = mat*64+h
__device__ __nv_bfloat16 g_wt_lo[192*CC];
__device__ int g_ctr  = 0;
__device__ int g_done = 0;

// split-tile partials: tile = b*32+qt (256 tiles), up to 4 segments each
__device__ float g_po[256*4*64*64];    // unnormalized O
__device__ float g_pm[256*4*64];       // row max (log2 domain)
__device__ float g_pl[256*4*64];       // row sum
__device__ int   g_cnt[256];           // arrival counters (zero-init)

// ---- mma.sync m16n8k16 bf16 (sm_80 baseline) ----
__device__ __forceinline__ void mma16816(float* c, const uint32_t* a, const uint32_t* b) {
    asm volatile(
        "mma.sync.aligned.m16n8k16.row.col.f32.bf16.bf16.f32 "
        "{%0,%1,%2,%3}, {%4,%5,%6,%7}, {%8,%9}, {%0,%1,%2,%3};"
        : "+f"(c[0]), "+f"(c[1]), "+f"(c[2]), "+f"(c[3])
        : "r"(a[0]), "r"(a[1]), "r"(a[2]), "r"(a[3]), "r"(b[0]), "r"(b[1]));
}
__device__ __forceinline__ void ldsm4(uint32_t* r, uint32_t addr) {
    asm volatile("ldmatrix.sync.aligned.m8n8.x4.shared.b16 {%0,%1,%2,%3}, [%4];"
        : "=r"(r[0]), "=r"(r[1]), "=r"(r[2]), "=r"(r[3]) : "r"(addr) : "memory");
}
#define CP16(dst, src) asm volatile("cp.async.cg.shared.global [%0], [%1], 16;" :: "r"(dst), "l"(src) : "memory")
#define CP_COMMIT()    asm volatile("cp.async.commit_group;" ::: "memory")
#define CP_WAIT0()     asm volatile("cp.async.wait_group 0;" ::: "memory")
#define CP_WAIT1()     asm volatile("cp.async.wait_group 1;" ::: "memory")

__device__ __forceinline__ uint32_t smem_u32(const void* p) {
    uint32_t a;
    asm("{ .reg .u64 t; cvta.to.shared.u64 t, %1; cvt.u32.u64 %0, t; }" : "=r"(a) : "l"(p));
    return a;
}
__device__ __forceinline__ float ex2(float x) {
    float y; asm("ex2.approx.f32 %0, %1;" : "=f"(y) : "f"(x)); return y;
}
__device__ __forceinline__ uint32_t hi2(float a, float b) {
    return ((uint32_t)__bfloat16_as_ushort(__float2bfloat16(b)) << 16) |
           (uint32_t)__bfloat16_as_ushort(__float2bfloat16(a));
}
__device__ __forceinline__ uint32_t lo2(float a, float b) {
    float ra = a - __bfloat162float(__float2bfloat16(a));
    float rb = b - __bfloat162float(__float2bfloat16(b));
    return hi2(ra, rb);
}

// ---------------------------------------------------------------------------
// Prep kernels
// ---------------------------------------------------------------------------
__global__ __launch_bounds__(256) void wprep_kernel(
    const float* __restrict__ Wq, const float* __restrict__ Wk,
    const float* __restrict__ Wv)
{
    int n = blockIdx.x;
    const float* W = (n < 64) ? Wq : (n < 128) ? Wk : Wv;
    int h = n & 63;
    for (int k = threadIdx.x; k < CC; k += 256) {
        float v = W[(size_t)k * HH + h];
        __nv_bfloat16 hi = __float2bfloat16(v);
        g_wt_hi[(size_t)n * CC + k] = hi;
        g_wt_lo[(size_t)n * CC + k] = __float2bfloat16(v - __bfloat162float(hi));
    }
}

__global__ __launch_bounds__(256) void xprep_kernel(const float* __restrict__ x)
{
    const int stride = gridDim.x * blockDim.x;
    for (int i = blockIdx.x * blockDim.x + threadIdx.x; i < BB*TT*CC/4; i += stride) {
        float4 v = *(const float4*)&x[(size_t)i * 4];
        uint2 hv, lv;
        hv.x = hi2(v.x, v.y);  hv.y = hi2(v.z, v.w);
        lv.x = lo2(v.x, v.y);  lv.y = lo2(v.z, v.w);
        *(uint2*)&g_xh[(size_t)i * 4] = hv;
        *(uint2*)&g_xl[(size_t)i * 4] = lv;
    }
}

// ---------------------------------------------------------------------------
// Projection GEMM (unchanged from R11): 128 CTAs x 256 thr, N=192, K=32 chunks
// ---------------------------------------------------------------------------
#define PROJ_SMEM 102400
#define PSS 25600

__global__ __launch_bounds__(256, 1) void proj_mma_kernel()
{
    extern __shared__ __nv_bfloat16 sb[];
    const uint32_t sbase = smem_u32(sb);

    const int tid  = threadIdx.x;
    const int wid  = tid >> 5;
    const int lane = tid & 31;
    const int g    = lane >> 2;
    const int tg   = lane & 3;
    const int m0   = blockIdx.x * 128;
    const int m0w  = (wid >> 1) * 32;
    const int n0w  = (wid & 1) * 96;

    const int m_off = (lane & 7) + ((lane >> 3) & 1) * 8;
    const int kA    = (lane >> 4) * 8;
    const int n_off = (lane & 7) + ((lane >> 4) & 1) * 8;
    const int kB    = ((lane >> 3) & 1) * 8;

    auto issue_chunk = [&](int kc, int s) {
        const int k0 = kc * 32;
        const uint32_t st = sbase + 2 * (s * PSS);
        #pragma unroll
        for (int t = 0; t < 4; t++) {
            int e = tid + t * 256;
            int arr = e >> 9;
            int ee  = e & 511;
            int row = ee >> 2, q = ee & 3;
            const __nv_bfloat16* src =
                (arr ? g_xl : g_xh) + (size_t)(m0 + row) * CC + k0 + q * 8;
            CP16(st + 2 * (arr * 5120 + row * 40 + q * 8), src);
        }
        #pragma unroll
        for (int t = 0; t < 6; t++) {
            int e = tid + t * 256;
            int arr = (e >= 768);
            int ee  = arr ? e - 768 : e;
            int row = ee >> 2, q = ee & 3;
            const __nv_bfloat16* src =
                (arr ? g_wt_lo : g_wt_hi) + (size_t)row * CC + k0 + q * 8;
            CP16(st + 2 * (10240 + arr * 7680 + row * 40 + q * 8), src);
        }
    };

    float acc[2][12][4];
    #pragma unroll
    for (int mt = 0; mt < 2; mt++)
        #pragma unroll
        for (int nt = 0; nt < 12; nt++)
            #pragma unroll
            for (int i = 0; i < 4; i++) acc[mt][nt][i] = 0.f;

    issue_chunk(0, 0); CP_COMMIT();
    issue_chunk(1, 1); CP_COMMIT();

    for (int kc = 0; kc < 32; kc++) {
        const int s = kc & 1;
        CP_WAIT1();
        __syncthreads();

        const uint32_t ah_b = sbase + 2 * (s * PSS);
        const uint32_t al_b = ah_b + 2 * 5120;
        const uint32_t bh_b = ah_b + 2 * 10240;
        const uint32_t bl_b = ah_b + 2 * 17920;

        #pragma unroll
        for (int ks = 0; ks < 32; ks += 16) {
            uint32_t ah[2][4], al[2][4];
            #pragma unroll
            for (int mt = 0; mt < 2; mt++) {
                int ro = (m0w + mt * 16 + m_off) * 40 + ks + kA;
                ldsm4(ah[mt], ah_b + 2 * ro);
                ldsm4(al[mt], al_b + 2 * ro);
            }
            #pragma unroll
            for (int p = 0; p < 6; p++) {
                int ro = (n0w + p * 16 + n_off) * 40 + ks + kB;
                uint32_t bh[4], bl[4];
                ldsm4(bh, bh_b + 2 * ro);
                ldsm4(bl, bl_b + 2 * ro);
                #pragma unroll
                for (int hf = 0; hf < 2; hf++) {
                    int nt = p * 2 + hf;
                    #pragma unroll
                    for (int mt = 0; mt < 2; mt++) {
                        mma16816(acc[mt][nt], ah[mt], bh + hf * 2);
                        mma16816(acc[mt][nt], ah[mt], bl + hf * 2);
                        mma16816(acc[mt][nt], al[mt], bh + hf * 2);
                    }
                }
            }
        }
        __syncthreads();
        if (kc + 2 < 32) issue_chunk(kc + 2, s);
        CP_COMMIT();
    }

    // ---- epilogue ----
    const int b  = m0 >> 11;
    const int t0 = m0 & 2047;
    const float QSC = 0.125f * 1.44269504088896f;
    __nv_bfloat16* sTh = sb;
    __nv_bfloat16* sTl = sb + 64 * 136;

    #pragma unroll
    for (int nt = 0; nt < 12; nt++) {
        int nbase = n0w + nt * 8;
        #pragma unroll
        for (int mt = 0; mt < 2; mt++) {
            int row = m0w + mt * 16 + g;
            float c0 = acc[mt][nt][0], c1 = acc[mt][nt][1];
            float c2 = acc[mt][nt][2], c3 = acc[mt][nt][3];
            if (nbase < 64) {
                c0 *= QSC; c1 *= QSC; c2 *= QSC; c3 *= QSC;
                size_t base0 = (size_t)(m0 + row) * HH + nbase + 2 * tg;
                size_t base1 = base0 + 8 * HH;
                *(uint32_t*)&g_qh[base0] = hi2(c0, c1);
                *(uint32_t*)&g_ql[base0] = lo2(c0, c1);
                *(uint32_t*)&g_qh[base1] = hi2(c2, c3);
                *(uint32_t*)&g_ql[base1] = lo2(c2, c3);
            } else if (nbase < 128) {
                size_t base0 = (size_t)(m0 + row) * HH + (nbase - 64) + 2 * tg;
                size_t base1 = base0 + 8 * HH;
                *(uint32_t*)&g_kh[base0] = hi2(c0, c1);
                *(uint32_t*)&g_kl[base0] = lo2(c0, c1);
                *(uint32_t*)&g_kh[base1] = hi2(c2, c3);
                *(uint32_t*)&g_kl[base1] = lo2(c2, c3);
            } else {
                int h = nbase - 128 + 2 * tg;
                __nv_bfloat16 h0 = __float2bfloat16(c0), h1 = __float2bfloat16(c1);
                __nv_bfloat16 h2 = __float2bfloat16(c2), h3 = __float2bfloat16(c3);
                sTh[h * 136 + row]           = h0;
                sTh[(h + 1) * 136 + row]     = h1;
                sTh[h * 136 + row + 8]       = h2;
                sTh[(h + 1) * 136 + row + 8] = h3;
                sTl[h * 136 + row]           = __float2bfloat16(c0 - __bfloat162float(h0));
                sTl[(h + 1) * 136 + row]     = __float2bfloat16(c1 - __bfloat162float(h1));
                sTl[h * 136 + row + 8]       = __float2bfloat16(c2 - __bfloat162float(h2));
                sTl[(h + 1) * 136 + row + 8] = __float2bfloat16(c3 - __bfloat162float(h3));
            }
        }
    }
    __syncthreads();
    #pragma unroll
    for (int t = 0; t < 8; t++) {
        int e   = tid + t * 256;
        int arr = e >> 10;
        int ee  = e & 1023;
        int h   = ee >> 4;
        int q   = ee & 15;
        uint4 v4 = *(const uint4*)&(arr ? sTl : sTh)[h * 136 + q * 8];
        __nv_bfloat16* dst = arr ? g_vtl : g_vth;
        *(uint4*)&dst[(size_t)(b * 64 + h) * 2048 + t0 + q * 8] = v4;
    }
}

// ---------------------------------------------------------------------------
// Attention: 640 jobs (segments <=8 chunks), 456 CTAs (3/SM via smem shrink).
// smem (bf16 units): stage s @ s*18432: Kh+0 Kl+4608 Vh+9216 Vl+13824.
// Q overlays stage1's V region (Qh@27648 Ql@32256) — consumed into regs
// before stage1 is ever filled.  Total 36864 units = 73728 B.
// ---------------------------------------------------------------------------
#define ATTN_CTAS 456
#define ATTN_JOBS 640
#define ATTN_SMEM 73728

__global__ __launch_bounds__(128, 3) void attn_mma_kernel(float* __restrict__ out)
{
    extern __shared__ __nv_bfloat16 sab[];
    const uint32_t sbase = smem_u32(sab);
    __shared__ int sJob;
    __shared__ int sLast;

    const int tid  = threadIdx.x;
    const int wid  = tid >> 5;
    const int lane = tid & 31;
    const int g    = lane >> 2;
    const int tg   = lane & 3;
    const int rw   = wid * 16;

    const int m_off = (lane & 7) + ((lane >> 3) & 1) * 8;
    const int kA    = (lane >> 4) * 8;
    const int n_off = (lane & 7) + ((lane >> 4) & 1) * 8;
    const int kB    = ((lane >> 3) & 1) * 8;

    for (;;) {
        if (tid == 0) sJob = atomicAdd(&g_ctr, 1);
        __syncthreads();
        const int job = sJob;
        if (job >= ATTN_JOBS) break;

        // ---- decode job (heavy-first; segments <= 8 chunks) ----
        int qt, b, seg, S;
        if (job < 256)      { int j = job;       qt = 31 - (j >> 5); b = (j >> 2) & 7; seg = j & 3;  S = 4; }
        else if (job < 448) { int j = job - 256; qt = 23 - (j / 24); int r = j % 24; b = r / 3; seg = r % 3; S = 3; }
        else if (job < 576) { int j = job - 448; qt = 15 - (j >> 4); b = (j >> 1) & 7; seg = j & 1;  S = 2; }
        else                { int j = job - 576; qt = 7  - (j >> 3); b = j & 7;        seg = 0;      S = 1; }
        const int L    = qt + 1;
        const int seg0 = (seg * L) / S;
        const int segn = ((seg + 1) * L) / S - seg0;
        const int q0   = qt * 64;

        auto issue_kv = [&](int t, int s) {
            const int kv0 = t * 64;
            const uint32_t st = sbase + 2 * (s * 18432);
            #pragma unroll
            for (int tt = 0; tt < 16; tt++) {
                int e = tid + tt * 128;
                int arr = e >> 9;            // 0:Kh 1:Kl 2:Vh 3:Vl
                int ee  = e & 511;
                int row = ee >> 3, q = ee & 7;
                const __nv_bfloat16* src;
                if (arr == 0)      src = g_kh  + ((size_t)b * TT + kv0 + row) * HH + q * 8;
                else if (arr == 1) src = g_kl  + ((size_t)b * TT + kv0 + row) * HH + q * 8;
                else if (arr == 2) src = g_vth + ((size_t)(b * 64 + row)) * 2048 + kv0 + q * 8;
                else               src = g_vtl + ((size_t)(b * 64 + row)) * 2048 + kv0 + q * 8;
                CP16(st + 2 * (arr * 4608 + row * 72 + q * 8), src);
            }
        };

        // G0: Q (into overlay) + KV(seg0) into stage 0
        #pragma unroll
        for (int tt = 0; tt < 8; tt++) {
            int e = tid + tt * 128;
            int arr = e >> 9;
            int ee  = e & 511;
            int row = ee >> 3, q = ee & 7;
            const __nv_bfloat16* src =
                (arr ? g_ql : g_qh) + ((size_t)b * TT + q0 + row) * HH + q * 8;
            CP16(sbase + 2 * (27648 + arr * 4608 + row * 72 + q * 8), src);
        }
        issue_kv(seg0, 0); CP_COMMIT();

        // wait all of G0, hoist Q into registers, then release the overlay
        CP_WAIT0();
        __syncthreads();
        uint32_t qfh[4][4], qfl[4][4];
        #pragma unroll
        for (int i = 0; i < 4; i++) {
            int ro = (rw + m_off) * 72 + i * 16 + kA;
            ldsm4(qfh[i], sbase + 2 * (27648 + ro));
            ldsm4(qfl[i], sbase + 2 * (32256 + ro));
        }
        __syncthreads();               // everyone done reading Q overlay
        if (segn >= 2) issue_kv(seg0 + 1, 1);
        CP_COMMIT();

        float m_i[2] = {-INFINITY, -INFINITY};
        float l_i[2] = {0.f, 0.f};
        float o[8][4];
        #pragma unroll
        for (int nt = 0; nt < 8; nt++)
            #pragma unroll
            for (int i = 0; i < 4; i++) o[nt][i] = 0.f;

        for (int tt = 0; tt < segn; tt++) {
            const int t = seg0 + tt;
            const int s = tt & 1;
            CP_WAIT1();
            __syncthreads();

            const uint32_t kh_b = sbase + 2 * (s * 18432);
            const uint32_t kl_b = kh_b + 2 * 4608;
            const uint32_t vh_b = kh_b + 2 * 9216;
            const uint32_t vl_b = kh_b + 2 * 13824;

            float sc[8][4];
            #pragma unroll
            for (int nt = 0; nt < 8; nt++)
                #pragma unroll
                for (int i = 0; i < 4; i++) sc[nt][i] = 0.f;

            #pragma unroll
            for (int i = 0; i < 4; i++) {
                int ks = i * 16;
                #pragma unroll
                for (int p = 0; p < 4; p++) {
                    int rb = (p * 16 + n_off) * 72 + ks + kB;
                    uint32_t bh[4], bl[4];
                    ldsm4(bh, kh_b + 2 * rb);
                    ldsm4(bl, kl_b + 2 * rb);
                    #pragma unroll
                    for (int hf = 0; hf < 2; hf++) {
                        int nt = p * 2 + hf;
                        mma16816(sc[nt], qfh[i], bh + hf * 2);
                        mma16816(sc[nt], qfh[i], bl + hf * 2);
                        mma16816(sc[nt], qfl[i], bh + hf * 2);
                    }
                }
            }

            if (t == qt) {   // diagonal chunk: causal mask
                int r0 = rw + g;
                #pragma unroll
                for (int nt = 0; nt < 8; nt++) {
                    int c0 = nt * 8 + 2 * tg;
                    if (c0     > r0)     sc[nt][0] = -INFINITY;
                    if (c0 + 1 > r0)     sc[nt][1] = -INFINITY;
                    if (c0     > r0 + 8) sc[nt][2] = -INFINITY;
                    if (c0 + 1 > r0 + 8) sc[nt][3] = -INFINITY;
                }
            }

            float mx0 = -INFINITY, mx1 = -INFINITY;
            #pragma unroll
            for (int nt = 0; nt < 8; nt++) {
                mx0 = fmaxf(mx0, fmaxf(sc[nt][0], sc[nt][1]));
                mx1 = fmaxf(mx1, fmaxf(sc[nt][2], sc[nt][3]));
            }
            mx0 = fmaxf(mx0, __shfl_xor_sync(0xffffffffu, mx0, 1));
            mx0 = fmaxf(mx0, __shfl_xor_sync(0xffffffffu, mx0, 2));
            mx1 = fmaxf(mx1, __shfl_xor_sync(0xffffffffu, mx1, 1));
            mx1 = fmaxf(mx1, __shfl_xor_sync(0xffffffffu, mx1, 2));

            float mn0 = fmaxf(m_i[0], mx0);
            float mn1 = fmaxf(m_i[1], mx1);
            float al0 = ex2(m_i[0] - mn0);
            float al1 = ex2(m_i[1] - mn1);
            m_i[0] = mn0;
            m_i[1] = mn1;
            #pragma unroll
            for (int nt = 0; nt < 8; nt++) {
                o[nt][0] *= al0; o[nt][1] *= al0;
                o[nt][2] *= al1; o[nt][3] *= al1;
            }

            float rs0 = 0.f, rs1 = 0.f;
            #pragma unroll
            for (int kk = 0; kk < 4; kk++) {
                int j0 = 2 * kk;
                float p00 = ex2(sc[j0][0] - mn0),     p01 = ex2(sc[j0][1] - mn0);
                float p02 = ex2(sc[j0][2] - mn1),     p03 = ex2(sc[j0][3] - mn1);
                float p10 = ex2(sc[j0 + 1][0] - mn0), p11 = ex2(sc[j0 + 1][1] - mn0);
                float p12 = ex2(sc[j0 + 1][2] - mn1), p13 = ex2(sc[j0 + 1][3] - mn1);
                rs0 += (p00 + p01) + (p10 + p11);
                rs1 += (p02 + p03) + (p12 + p13);
                uint32_t ph[4], pl[4];
                ph[0] = hi2(p00, p01);  pl[0] = lo2(p00, p01);
                ph[1] = hi2(p02, p03);  pl[1] = lo2(p02, p03);
                ph[2] = hi2(p10, p11);  pl[2] = lo2(p10, p11);
                ph[3] = hi2(p12, p13);  pl[3] = lo2(p12, p13);
                #pragma unroll
                for (int p = 0; p < 4; p++) {
                    int rb = (p * 16 + n_off) * 72 + kk * 16 + kB;
                    uint32_t bvh[4], bvl[4];
                    ldsm4(bvh, vh_b + 2 * rb);
                    ldsm4(bvl, vl_b + 2 * rb);
                    #pragma unroll
                    for (int hf = 0; hf < 2; hf++) {
                        int nt = p * 2 + hf;
                        mma16816(o[nt], ph, bvh + hf * 2);
                        mma16816(o[nt], ph, bvl + hf * 2);
                        mma16816(o[nt], pl, bvh + hf * 2);
                    }
                }
            }
            rs0 += __shfl_xor_sync(0xffffffffu, rs0, 1);
            rs0 += __shfl_xor_sync(0xffffffffu, rs0, 2);
            rs1 += __shfl_xor_sync(0xffffffffu, rs1, 1);
            rs1 += __shfl_xor_sync(0xffffffffu, rs1, 2);
            l_i[0] = l_i[0] * al0 + rs0;
            l_i[1] = l_i[1] * al1 + rs1;

            __syncthreads();
            if (tt + 2 < segn) issue_kv(seg0 + tt + 2, s);
            CP_COMMIT();
        }

        // ---- epilogue ----
        if (S == 1) {
            float inv0 = 1.f / l_i[0];
            float inv1 = 1.f / l_i[1];
            int row0 = q0 + rw + g;
            #pragma unroll
            for (int nt = 0; nt < 8; nt++) {
                *(float2*)&out[((size_t)b * TT + row0) * HH + nt * 8 + 2 * tg] =
                    make_float2(o[nt][0] * inv0, o[nt][1] * inv0);
                *(float2*)&out[((size_t)b * TT + row0 + 8) * HH + nt * 8 + 2 * tg] =
                    make_float2(o[nt][2] * inv1, o[nt][3] * inv1);
            }
        } else {
            const int tile = b * 32 + qt;
            float* po = g_po + (size_t)(tile * 4 + seg) * 4096;
            float* pm = g_pm + (size_t)(tile * 4 + seg) * 64;
            float* pl = g_pl + (size_t)(tile * 4 + seg) * 64;
            int r0 = rw + g;
            #pragma unroll
            for (int nt = 0; nt < 8; nt++) {
                *(float2*)&po[r0 * 64 + nt * 8 + 2 * tg]       = make_float2(o[nt][0], o[nt][1]);
                *(float2*)&po[(r0 + 8) * 64 + nt * 8 + 2 * tg] = make_float2(o[nt][2], o[nt][3]);
            }
            if (tg == 0) {
                pm[r0] = m_i[0];  pl[r0] = l_i[0];
                pm[r0 + 8] = m_i[1];  pl[r0 + 8] = l_i[1];
            }
            __threadfence();
            __syncthreads();
            if (tid == 0) sLast = atomicAdd(&g_cnt[tile], 1);
            __syncthreads();
            if (sLast == S - 1) {
                __threadfence();
                int r  = tid >> 1;           // 0..63
                int c0 = (tid & 1) * 32;
                float ms[4], ls[4];
                float mm = -INFINITY;
                for (int s2 = 0; s2 < S; s2++) {
                    ms[s2] = g_pm[(size_t)(tile * 4 + s2) * 64 + r];
                    ls[s2] = g_pl[(size_t)(tile * 4 + s2) * 64 + r];
                    mm = fmaxf(mm, ms[s2]);
                }
                float a[4], lsum = 0.f;
                for (int s2 = 0; s2 < S; s2++) {
                    a[s2] = ex2(ms[s2] - mm);
                    lsum += ls[s2] * a[s2];
                }
                float inv = 1.f / lsum;
                float* dst = &out[((size_t)b * TT + q0 + r) * HH + c0];
                #pragma unroll 8
                for (int c = 0; c < 32; c++) {
                    float acc2 = 0.f;
                    for (int s2 = 0; s2 < S; s2++)
                        acc2 += g_po[(size_t)(tile * 4 + s2) * 4096 + r * 64 + c0 + c] * a[s2];
                    dst[c] = acc2 * inv;
                }
                if (tid == 0) g_cnt[tile] = 0;    // reset for next graph replay
            }
        }
    }

    if (tid == 0) {
        if (atomicAdd(&g_done, 1) == ATTN_CTAS - 1) {
            g_ctr  = 0;
            g_done = 0;
        }
    }
}

extern "C" void kernel_launch(void* const* d_in, const int* in_sizes, int n_in,
                              void* d_out, int out_size)
{
    const float* x  = (const float*)d_in[0];
    const float* Wq = (const float*)d_in[1];
    const float* Wk = (const float*)d_in[2];
    const float* Wv = (const float*)d_in[3];
    float* out = (float*)d_out;

    cudaFuncSetAttribute(proj_mma_kernel,
                         cudaFuncAttributeMaxDynamicSharedMemorySize, PROJ_SMEM);
    cudaFuncSetAttribute(attn_mma_kernel,
                         cudaFuncAttributeMaxDynamicSharedMemorySize, ATTN_SMEM);

    wprep_kernel<<<192, 256>>>(Wq, Wk, Wv);
    xprep_kernel<<<2048, 256>>>(x);
    proj_mma_kernel<<<BB * TT / 128, 256, PROJ_SMEM>>>();
    attn_mma_kernel<<<ATTN_CTAS, 128, ATTN_SMEM>>>(out);
}

// round 13
// speedup vs baseline: 1.1216x; 1.1216x over previous
#include <cuda_runtime.h>
#include <cuda_bf16.h>
#include <math.h>
#include <cstdint>

#define BB 8
#define TT 2048
#define CC 1024
#define HH 64

// bf16 hi/lo tensors
__device__ __nv_bfloat16 g_xh[BB*TT*CC], g_xl[BB*TT*CC];   // x  [m][c]
__device__ __nv_bfloat16 g_qh[BB*TT*HH], g_ql[BB*TT*HH];   // q  [b][t][h] (x 0.125*log2e)
__device__ __nv_bfloat16 g_kh[BB*TT*HH], g_kl[BB*TT*HH];   // k  [b][t][h]
__device__ __nv_bfloat16 g_vth[BB*HH*TT], g_vtl[BB*HH*TT]; // v^T [b][h][t]
__device__ __nv_bfloat16 g_wt_hi[192*CC];                  // W^T [n][k], n = mat*64+h
__device__ __nv_bfloat16 g_wt_lo[192*CC];
__device__ int g_ctr  = 0;
__device__ int g_done = 0;

// split-tile partials: tiles with qt in [16,31], 2 segments each
__device__ float g_po[8*16*2*64*64];   // unnormalized O
__device__ float g_pm[8*16*2*64];      // row max (log2 domain)
__device__ float g_pl[8*16*2*64];      // row sum
__device__ int   g_cnt[8*16];          // arrival counters (zero-init)

// ---- mma.sync m16n8k16 bf16 (sm_80 baseline) ----
__device__ __forceinline__ void mma16816(float* c, const uint32_t* a, const uint32_t* b) {
    asm volatile(
        "mma.sync.aligned.m16n8k16.row.col.f32.bf16.bf16.f32 "
        "{%0,%1,%2,%3}, {%4,%5,%6,%7}, {%8,%9}, {%0,%1,%2,%3};"
        : "+f"(c[0]), "+f"(c[1]), "+f"(c[2]), "+f"(c[3])
        : "r"(a[0]), "r"(a[1]), "r"(a[2]), "r"(a[3]), "r"(b[0]), "r"(b[1]));
}
__device__ __forceinline__ void ldsm4(uint32_t* r, uint32_t addr) {
    asm volatile("ldmatrix.sync.aligned.m8n8.x4.shared.b16 {%0,%1,%2,%3}, [%4];"
        : "=r"(r[0]), "=r"(r[1]), "=r"(r[2]), "=r"(r[3]) : "r"(addr) : "memory");
}
#define CP16(dst, src) asm volatile("cp.async.cg.shared.global [%0], [%1], 16;" :: "r"(dst), "l"(src) : "memory")
#define CP_COMMIT()    asm volatile("cp.async.commit_group;" ::: "memory")
#define CP_WAIT1()     asm volatile("cp.async.wait_group 1;" ::: "memory")

__device__ __forceinline__ uint32_t smem_u32(const void* p) {
    uint32_t a;
    asm("{ .reg .u64 t; cvta.to.shared.u64 t, %1; cvt.u32.u64 %0, t; }" : "=r"(a) : "l"(p));
    return a;
}
__device__ __forceinline__ float ex2(float x) {
    float y; asm("ex2.approx.f32 %0, %1;" : "=f"(y) : "f"(x)); return y;
}
__device__ __forceinline__ uint32_t hi2(float a, float b) {
    return ((uint32_t)__bfloat16_as_ushort(__float2bfloat16(b)) << 16) |
           (uint32_t)__bfloat16_as_ushort(__float2bfloat16(a));
}
__device__ __forceinline__ uint32_t lo2(float a, float b) {
    float ra = a - __bfloat162float(__float2bfloat16(a));
    float rb = b - __bfloat162float(__float2bfloat16(b));
    return hi2(ra, rb);
}

// ---------------------------------------------------------------------------
// Prep kernels
// ---------------------------------------------------------------------------
__global__ __launch_bounds__(256) void wprep_kernel(
    const float* __restrict__ Wq, const float* __restrict__ Wk,
    const float* __restrict__ Wv)
{
    int n = blockIdx.x;
    const float* W = (n < 64) ? Wq : (n < 128) ? Wk : Wv;
    int h = n & 63;
    for (int k = threadIdx.x; k < CC; k += 256) {
        float v = W[(size_t)k * HH + h];
        __nv_bfloat16 hi = __float2bfloat16(v);
        g_wt_hi[(size_t)n * CC + k] = hi;
        g_wt_lo[(size_t)n * CC + k] = __float2bfloat16(v - __bfloat162float(hi));
    }
}

__global__ __launch_bounds__(256) void xprep_kernel(const float* __restrict__ x)
{
    const int stride = gridDim.x * blockDim.x;
    for (int i = blockIdx.x * blockDim.x + threadIdx.x; i < BB*TT*CC/4; i += stride) {
        float4 v = *(const float4*)&x[(size_t)i * 4];
        uint2 hv, lv;
        hv.x = hi2(v.x, v.y);  hv.y = hi2(v.z, v.w);
        lv.x = lo2(v.x, v.y);  lv.y = lo2(v.z, v.w);
        *(uint2*)&g_xh[(size_t)i * 4] = hv;
        *(uint2*)&g_xl[(size_t)i * 4] = lv;
    }
}

// ---------------------------------------------------------------------------
// Projection GEMM: 64-row M tiles -> 256 CTAs (2/SM), 256 thr (8 warps 4Mx2N,
// warp tile 16m x 96n).  K chunks of 32, cp.async double-buffered.
// smem per stage (bf16 units): Ah@0(2560) Al@2560 Bh@5120(7680) Bl@12800
// stage stride 20480; 2 stages = 40960 units = 81920 B -> 2 CTAs/SM.
// ---------------------------------------------------------------------------
#define PROJ_SMEM 81920
#define PSS 20480

__global__ __launch_bounds__(256, 2) void proj_mma_kernel()
{
    extern __shared__ __nv_bfloat16 sb[];
    const uint32_t sbase = smem_u32(sb);

    const int tid  = threadIdx.x;
    const int wid  = tid >> 5;
    const int lane = tid & 31;
    const int g    = lane >> 2;
    const int tg   = lane & 3;
    const int m0   = blockIdx.x * 64;
    const int m0w  = (wid >> 1) * 16;
    const int n0w  = (wid & 1) * 96;

    const int m_off = (lane & 7) + ((lane >> 3) & 1) * 8;
    const int kA    = (lane >> 4) * 8;
    const int n_off = (lane & 7) + ((lane >> 4) & 1) * 8;
    const int kB    = ((lane >> 3) & 1) * 8;

    auto issue_chunk = [&](int kc, int s) {
        const int k0 = kc * 32;
        const uint32_t st = sbase + 2 * (s * PSS);
        #pragma unroll
        for (int t = 0; t < 2; t++) {            // A: 512 x 16B (64 rows, hi+lo)
            int e = tid + t * 256;
            int arr = e >> 8;
            int ee  = e & 255;
            int row = ee >> 2, q = ee & 3;
            const __nv_bfloat16* src =
                (arr ? g_xl : g_xh) + (size_t)(m0 + row) * CC + k0 + q * 8;
            CP16(st + 2 * (arr * 2560 + row * 40 + q * 8), src);
        }
        #pragma unroll
        for (int t = 0; t < 6; t++) {            // B: 1536 x 16B
            int e = tid + t * 256;
            int arr = (e >= 768);
            int ee  = arr ? e - 768 : e;
            int row = ee >> 2, q = ee & 3;
            const __nv_bfloat16* src =
                (arr ? g_wt_lo : g_wt_hi) + (size_t)row * CC + k0 + q * 8;
            CP16(st + 2 * (5120 + arr * 7680 + row * 40 + q * 8), src);
        }
    };

    float acc[12][4];
    #pragma unroll
    for (int nt = 0; nt < 12; nt++)
        #pragma unroll
        for (int i = 0; i < 4; i++) acc[nt][i] = 0.f;

    issue_chunk(0, 0); CP_COMMIT();
    issue_chunk(1, 1); CP_COMMIT();

    for (int kc = 0; kc < 32; kc++) {
        const int s = kc & 1;
        CP_WAIT1();
        __syncthreads();

        const uint32_t ah_b = sbase + 2 * (s * PSS);
        const uint32_t al_b = ah_b + 2 * 2560;
        const uint32_t bh_b = ah_b + 2 * 5120;
        const uint32_t bl_b = ah_b + 2 * 12800;

        #pragma unroll
        for (int ks = 0; ks < 32; ks += 16) {
            uint32_t ah[4], al[4];
            int ro = (m0w + m_off) * 40 + ks + kA;
            ldsm4(ah, ah_b + 2 * ro);
            ldsm4(al, al_b + 2 * ro);
            #pragma unroll
            for (int p = 0; p < 6; p++) {
                int rb = (n0w + p * 16 + n_off) * 40 + ks + kB;
                uint32_t bh[4], bl[4];
                ldsm4(bh, bh_b + 2 * rb);
                ldsm4(bl, bl_b + 2 * rb);
                #pragma unroll
                for (int hf = 0; hf < 2; hf++) {
                    int nt = p * 2 + hf;
                    mma16816(acc[nt], ah, bh + hf * 2);
                    mma16816(acc[nt], ah, bl + hf * 2);
                    mma16816(acc[nt], al, bh + hf * 2);
                }
            }
        }
        __syncthreads();
        if (kc + 2 < 32) issue_chunk(kc + 2, s);
        CP_COMMIT();
    }

    // ---- epilogue: Q (x 0.125*log2e) / K -> [t][h] hi/lo; V -> transpose ----
    const int b  = m0 >> 11;
    const int t0 = m0 & 2047;
    const float QSC = 0.125f * 1.44269504088896f;
    __nv_bfloat16* sTh = sb;               // [64 h][72] (64 t cols used)
    __nv_bfloat16* sTl = sb + 64 * 72;

    #pragma unroll
    for (int nt = 0; nt < 12; nt++) {
        int nbase = n0w + nt * 8;
        int row = m0w + g;                 // local 0..63 (and row+8)
        float c0 = acc[nt][0], c1 = acc[nt][1];
        float c2 = acc[nt][2], c3 = acc[nt][3];
        if (nbase < 64) {
            c0 *= QSC; c1 *= QSC; c2 *= QSC; c3 *= QSC;
            size_t base0 = (size_t)(m0 + row) * HH + nbase + 2 * tg;
            size_t base1 = base0 + 8 * HH;
            *(uint32_t*)&g_qh[base0] = hi2(c0, c1);
            *(uint32_t*)&g_ql[base0] = lo2(c0, c1);
            *(uint32_t*)&g_qh[base1] = hi2(c2, c3);
            *(uint32_t*)&g_ql[base1] = lo2(c2, c3);
        } else if (nbase < 128) {
            size_t base0 = (size_t)(m0 + row) * HH + (nbase - 64) + 2 * tg;
            size_t base1 = base0 + 8 * HH;
            *(uint32_t*)&g_kh[base0] = hi2(c0, c1);
            *(uint32_t*)&g_kl[base0] = lo2(c0, c1);
            *(uint32_t*)&g_kh[base1] = hi2(c2, c3);
            *(uint32_t*)&g_kl[base1] = lo2(c2, c3);
        } else {
            int h = nbase - 128 + 2 * tg;
            __nv_bfloat16 h0 = __float2bfloat16(c0), h1 = __float2bfloat16(c1);
            __nv_bfloat16 h2 = __float2bfloat16(c2), h3 = __float2bfloat16(c3);
            sTh[h * 72 + row]           = h0;
            sTh[(h + 1) * 72 + row]     = h1;
            sTh[h * 72 + row + 8]       = h2;
            sTh[(h + 1) * 72 + row + 8] = h3;
            sTl[h * 72 + row]           = __float2bfloat16(c0 - __bfloat162float(h0));
            sTl[(h + 1) * 72 + row]     = __float2bfloat16(c1 - __bfloat162float(h1));
            sTl[h * 72 + row + 8]       = __float2bfloat16(c2 - __bfloat162float(h2));
            sTl[(h + 1) * 72 + row + 8] = __float2bfloat16(c3 - __bfloat162float(h3));
        }
    }
    __syncthreads();
    // coalesced V^T copy: 64 h-rows x 64 t, hi+lo  (1024 x 16B)
    #pragma unroll
    for (int t = 0; t < 4; t++) {
        int e   = tid + t * 256;
        int arr = e >> 9;
        int ee  = e & 511;
        int h   = ee >> 3;
        int q   = ee & 7;
        uint4 v4 = *(const uint4*)&(arr ? sTl : sTh)[h * 72 + q * 8];
        __nv_bfloat16* dst = arr ? g_vtl : g_vth;
        *(uint4*)&dst[(size_t)(b * 64 + h) * 2048 + t0 + q * 8] = v4;
    }
}

// ---------------------------------------------------------------------------
// Attention (R11 config — best measured): KV-split jobs, qt>=16 split in 2,
// 384 jobs, 304 CTAs.  smem: Qh@0 Ql@4608; stage s @9216+s*18432:
//   Kh+0 Kl+4608 Vh+9216 Vl+13824.  total 92160 B
// ---------------------------------------------------------------------------
#define ATTN_CTAS 304
#define ATTN_JOBS 384
#define ATTN_SMEM 92160

__global__ __launch_bounds__(128, 1) void attn_mma_kernel(float* __restrict__ out)
{
    extern __shared__ __nv_bfloat16 sab[];
    const uint32_t sbase = smem_u32(sab);
    __shared__ int sJob;
    __shared__ int sLast;

    const int tid  = threadIdx.x;
    const int wid  = tid >> 5;
    const int lane = tid & 31;
    const int g    = lane >> 2;
    const int tg   = lane & 3;
    const int rw   = wid * 16;

    const int m_off = (lane & 7) + ((lane >> 3) & 1) * 8;
    const int kA    = (lane >> 4) * 8;
    const int n_off = (lane & 7) + ((lane >> 4) & 1) * 8;
    const int kB    = ((lane >> 3) & 1) * 8;

    for (;;) {
        if (tid == 0) sJob = atomicAdd(&g_ctr, 1);
        __syncthreads();
        const int job = sJob;
        if (job >= ATTN_JOBS) break;

        int qt, b, segid, seg0, segn, split;
        if (job < 256) {
            qt    = 31 - (job >> 4);
            b     = (job >> 1) & 7;
            segid = job & 1;
            split = 1;
            int total = qt + 1;
            int h = (total + 1) >> 1;
            if (segid == 0) { seg0 = 0; segn = h; }
            else            { seg0 = h; segn = total - h; }
        } else {
            int j2 = job - 256;
            qt = 15 - (j2 >> 3);
            b  = j2 & 7;
            segid = 0; split = 0; seg0 = 0; segn = qt + 1;
        }
        const int q0 = qt * 64;

        auto issue_kv = [&](int t, int s) {
            const int kv0 = t * 64;
            const uint32_t st = sbase + 2 * (9216 + s * 18432);
            #pragma unroll
            for (int tt = 0; tt < 16; tt++) {
                int e = tid + tt * 128;
                int arr = e >> 9;
                int ee  = e & 511;
                int row = ee >> 3, q = ee & 7;
                const __nv_bfloat16* src;
                if (arr == 0)      src = g_kh  + ((size_t)b * TT + kv0 + row) * HH + q * 8;
                else if (arr == 1) src = g_kl  + ((size_t)b * TT + kv0 + row) * HH + q * 8;
                else if (arr == 2) src = g_vth + ((size_t)(b * 64 + row)) * 2048 + kv0 + q * 8;
                else               src = g_vtl + ((size_t)(b * 64 + row)) * 2048 + kv0 + q * 8;
                CP16(st + 2 * (arr * 4608 + row * 72 + q * 8), src);
            }
        };

        #pragma unroll
        for (int tt = 0; tt < 8; tt++) {
            int e = tid + tt * 128;
            int arr = e >> 9;
            int ee  = e & 511;
            int row = ee >> 3, q = ee & 7;
            const __nv_bfloat16* src =
                (arr ? g_ql : g_qh) + ((size_t)b * TT + q0 + row) * HH + q * 8;
            CP16(sbase + 2 * (arr * 4608 + row * 72 + q * 8), src);
        }
        issue_kv(seg0, 0); CP_COMMIT();
        if (segn >= 2) issue_kv(seg0 + 1, 1);
        CP_COMMIT();

        CP_WAIT1();
        __syncthreads();
        uint32_t qfh[4][4], qfl[4][4];
        #pragma unroll
        for (int i = 0; i < 4; i++) {
            int ro = (rw + m_off) * 72 + i * 16 + kA;
            ldsm4(qfh[i], sbase + 2 * ro);
            ldsm4(qfl[i], sbase + 2 * (4608 + ro));
        }

        float m_i[2] = {-INFINITY, -INFINITY};
        float l_i[2] = {0.f, 0.f};
        float o[8][4];
        #pragma unroll
        for (int nt = 0; nt < 8; nt++)
            #pragma unroll
            for (int i = 0; i < 4; i++) o[nt][i] = 0.f;

        for (int tt = 0; tt < segn; tt++) {
            const int t = seg0 + tt;
            const int s = tt & 1;
            CP_WAIT1();
            __syncthreads();

            const uint32_t kh_b = sbase + 2 * (9216 + s * 18432);
            const uint32_t kl_b = kh_b + 2 * 4608;
            const uint32_t vh_b = kh_b + 2 * 9216;
            const uint32_t vl_b = kh_b + 2 * 13824;

            float sc[8][4];
            #pragma unroll
            for (int nt = 0; nt < 8; nt++)
                #pragma unroll
                for (int i = 0; i < 4; i++) sc[nt][i] = 0.f;

            #pragma unroll
            for (int i = 0; i < 4; i++) {
                int ks = i * 16;
                #pragma unroll
                for (int p = 0; p < 4; p++) {
                    int rb = (p * 16 + n_off) * 72 + ks + kB;
                    uint32_t bh[4], bl[4];
                    ldsm4(bh, kh_b + 2 * rb);
                    ldsm4(bl, kl_b + 2 * rb);
                    #pragma unroll
                    for (int hf = 0; hf < 2; hf++) {
                        int nt = p * 2 + hf;
                        mma16816(sc[nt], qfh[i], bh + hf * 2);
                        mma16816(sc[nt], qfh[i], bl + hf * 2);
                        mma16816(sc[nt], qfl[i], bh + hf * 2);
                    }
                }
            }

            if (t == qt) {
                int r0 = rw + g;
                #pragma unroll
                for (int nt = 0; nt < 8; nt++) {
                    int c0 = nt * 8 + 2 * tg;
                    if (c0     > r0)     sc[nt][0] = -INFINITY;
                    if (c0 + 1 > r0)     sc[nt][1] = -INFINITY;
                    if (c0     > r0 + 8) sc[nt][2] = -INFINITY;
                    if (c0 + 1 > r0 + 8) sc[nt][3] = -INFINITY;
                }
            }

            float mx0 = -INFINITY, mx1 = -INFINITY;
            #pragma unroll
            for (int nt = 0; nt < 8; nt++) {
                mx0 = fmaxf(mx0, fmaxf(sc[nt][0], sc[nt][1]));
                mx1 = fmaxf(mx1, fmaxf(sc[nt][2], sc[nt][3]));
            }
            mx0 = fmaxf(mx0, __shfl_xor_sync(0xffffffffu, mx0, 1));
            mx0 = fmaxf(mx0, __shfl_xor_sync(0xffffffffu, mx0, 2));
            mx1 = fmaxf(mx1, __shfl_xor_sync(0xffffffffu, mx1, 1));
            mx1 = fmaxf(mx1, __shfl_xor_sync(0xffffffffu, mx1, 2));

            float mn0 = fmaxf(m_i[0], mx0);
            float mn1 = fmaxf(m_i[1], mx1);
            float al0 = ex2(m_i[0] - mn0);
            float al1 = ex2(m_i[1] - mn1);
            m_i[0] = mn0;
            m_i[1] = mn1;
            #pragma unroll
            for (int nt = 0; nt < 8; nt++) {
                o[nt][0] *= al0; o[nt][1] *= al0;
                o[nt][2] *= al1; o[nt][3] *= al1;
            }

            float rs0 = 0.f, rs1 = 0.f;
            #pragma unroll
            for (int kk = 0; kk < 4; kk++) {
                int j0 = 2 * kk;
                float p00 = ex2(sc[j0][0] - mn0),     p01 = ex2(sc[j0][1] - mn0);
                float p02 = ex2(sc[j0][2] - mn1),     p03 = ex2(sc[j0][3] - mn1);
                float p10 = ex2(sc[j0 + 1][0] - mn0), p11 = ex2(sc[j0 + 1][1] - mn0);
                float p12 = ex2(sc[j0 + 1][2] - mn1), p13 = ex2(sc[j0 + 1][3] - mn1);
                rs0 += (p00 + p01) + (p10 + p11);
                rs1 += (p02 + p03) + (p12 + p13);
                uint32_t ph[4], pl[4];
                ph[0] = hi2(p00, p01);  pl[0] = lo2(p00, p01);
                ph[1] = hi2(p02, p03);  pl[1] = lo2(p02, p03);
                ph[2] = hi2(p10, p11);  pl[2] = lo2(p10, p11);
                ph[3] = hi2(p12, p13);  pl[3] = lo2(p12, p13);
                #pragma unroll
                for (int p = 0; p < 4; p++) {
                    int rb = (p * 16 + n_off) * 72 + kk * 16 + kB;
                    uint32_t bvh[4], bvl[4];
                    ldsm4(bvh, vh_b + 2 * rb);
                    ldsm4(bvl, vl_b + 2 * rb);
                    #pragma unroll
                    for (int hf = 0; hf < 2; hf++) {
                        int nt = p * 2 + hf;
                        mma16816(o[nt], ph, bvh + hf * 2);
                        mma16816(o[nt], ph, bvl + hf * 2);
                        mma16816(o[nt], pl, bvh + hf * 2);
                    }
                }
            }
            rs0 += __shfl_xor_sync(0xffffffffu, rs0, 1);
            rs0 += __shfl_xor_sync(0xffffffffu, rs0, 2);
            rs1 += __shfl_xor_sync(0xffffffffu, rs1, 1);
            rs1 += __shfl_xor_sync(0xffffffffu, rs1, 2);
            l_i[0] = l_i[0] * al0 + rs0;
            l_i[1] = l_i[1] * al1 + rs1;

            __syncthreads();
            if (tt + 2 < segn) issue_kv(seg0 + tt + 2, s);
            CP_COMMIT();
        }

        if (!split) {
            float inv0 = 1.f / l_i[0];
            float inv1 = 1.f / l_i[1];
            int row0 = q0 + rw + g;
            #pragma unroll
            for (int nt = 0; nt < 8; nt++) {
                *(float2*)&out[((size_t)b * TT + row0) * HH + nt * 8 + 2 * tg] =
                    make_float2(o[nt][0] * inv0, o[nt][1] * inv0);
                *(float2*)&out[((size_t)b * TT + row0 + 8) * HH + nt * 8 + 2 * tg] =
                    make_float2(o[nt][2] * inv1, o[nt][3] * inv1);
            }
        } else {
            const int qi   = qt - 16;
            const int tile = b * 16 + qi;
            float* po = g_po + (size_t)(tile * 2 + segid) * 4096;
            float* pm = g_pm + (size_t)(tile * 2 + segid) * 64;
            float* pl = g_pl + (size_t)(tile * 2 + segid) * 64;
            int r0 = rw + g;
            #pragma unroll
            for (int nt = 0; nt < 8; nt++) {
                *(float2*)&po[r0 * 64 + nt * 8 + 2 * tg]       = make_float2(o[nt][0], o[nt][1]);
                *(float2*)&po[(r0 + 8) * 64 + nt * 8 + 2 * tg] = make_float2(o[nt][2], o[nt][3]);
            }
            if (tg == 0) {
                pm[r0] = m_i[0];  pl[r0] = l_i[0];
                pm[r0 + 8] = m_i[1];  pl[r0 + 8] = l_i[1];
            }
            __threadfence();
            __syncthreads();
            if (tid == 0) sLast = atomicAdd(&g_cnt[tile], 1);
            __syncthreads();
            if (sLast == 1) {
                __threadfence();
                const float* po0 = g_po + (size_t)(tile * 2 + 0) * 4096;
                const float* po1 = g_po + (size_t)(tile * 2 + 1) * 4096;
                const float* pm0 = g_pm + (size_t)(tile * 2 + 0) * 64;
                const float* pm1 = g_pm + (size_t)(tile * 2 + 1) * 64;
                const float* pl0 = g_pl + (size_t)(tile * 2 + 0) * 64;
                const float* pl1 = g_pl + (size_t)(tile * 2 + 1) * 64;
                int r  = tid >> 1;
                int c0 = (tid & 1) * 32;
                float m0v = pm0[r], m1v = pm1[r];
                float mm = fmaxf(m0v, m1v);
                float a0 = ex2(m0v - mm), a1 = ex2(m1v - mm);
                float inv = 1.f / (pl0[r] * a0 + pl1[r] * a1);
                float* dst = &out[((size_t)b * TT + q0 + r) * HH + c0];
                #pragma unroll 8
                for (int c = 0; c < 32; c++)
                    dst[c] = (po0[r * 64 + c0 + c] * a0 + po1[r * 64 + c0 + c] * a1) * inv;
                if (tid == 0) g_cnt[tile] = 0;
            }
        }
    }

    if (tid == 0) {
        if (atomicAdd(&g_done, 1) == ATTN_CTAS - 1) {
            g_ctr  = 0;
            g_done = 0;
        }
    }
}

extern "C" void kernel_launch(void* const* d_in, const int* in_sizes, int n_in,
                              void* d_out, int out_size)
{
    const float* x  = (const float*)d_in[0];
    const float* Wq = (const float*)d_in[1];
    const float* Wk = (const float*)d_in[2];
    const float* Wv = (const float*)d_in[3];
    float* out = (float*)d_out;

    cudaFuncSetAttribute(proj_mma_kernel,
                         cudaFuncAttributeMaxDynamicSharedMemorySize, PROJ_SMEM);
    cudaFuncSetAttribute(attn_mma_kernel,
                         cudaFuncAttributeMaxDynamicSharedMemorySize, ATTN_SMEM);

    wprep_kernel<<<192, 256>>>(Wq, Wk, Wv);
    xprep_kernel<<<2048, 256>>>(x);
    proj_mma_kernel<<<BB * TT / 64, 256, PROJ_SMEM>>>();
    attn_mma_kernel<<<ATTN_CTAS, 128, ATTN_SMEM>>>(out);
}

// round 14
// speedup vs baseline: 1.1982x; 1.0683x over previous
#include <cuda_runtime.h>
#include <cuda_bf16.h>
#include <math.h>
#include <cstdint>

#define BB 8
#define TT 2048
#define CC 1024
#define HH 64

// x / W prep tensors (proj inputs, unchanged layout)
__device__ __nv_bfloat16 g_xh[BB*TT*CC], g_xl[BB*TT*CC];   // x  [m][c]
__device__ __nv_bfloat16 g_wt_hi[192*CC];                  // W^T [n][k], n = mat*64+h
__device__ __nv_bfloat16 g_wt_lo[192*CC];

// Q/K/V^T as blocked swizzled 64x64 tiles: [b*32+tile][hi/lo][4096 units]
// unit(row,col) = row*64 + (((col>>3) ^ (row&7))<<3) + (col&7)
__device__ __nv_bfloat16 g_qT[8*32*2*4096];   // q tiles [t-row][h-col], pre-scaled x0.125*log2e
__device__ __nv_bfloat16 g_kT[8*32*2*4096];   // k tiles [t-row][h-col]
__device__ __nv_bfloat16 g_vT[8*32*2*4096];   // v^T tiles [h-row][t-col]

__device__ int g_ctr  = 0;
__device__ int g_done = 0;

// split-tile partials (qt>=16, 2 segments)
__device__ float g_po[8*16*2*64*64];
__device__ float g_pm[8*16*2*64];
__device__ float g_pl[8*16*2*64];
__device__ int   g_cnt[8*16];

// ---- mma.sync m16n8k16 bf16 (sm_80 baseline) ----
__device__ __forceinline__ void mma16816(float* c, const uint32_t* a, const uint32_t* b) {
    asm volatile(
        "mma.sync.aligned.m16n8k16.row.col.f32.bf16.bf16.f32 "
        "{%0,%1,%2,%3}, {%4,%5,%6,%7}, {%8,%9}, {%0,%1,%2,%3};"
        : "+f"(c[0]), "+f"(c[1]), "+f"(c[2]), "+f"(c[3])
        : "r"(a[0]), "r"(a[1]), "r"(a[2]), "r"(a[3]), "r"(b[0]), "r"(b[1]));
}
__device__ __forceinline__ void ldsm4(uint32_t* r, uint32_t addr) {
    asm volatile("ldmatrix.sync.aligned.m8n8.x4.shared.b16 {%0,%1,%2,%3}, [%4];"
        : "=r"(r[0]), "=r"(r[1]), "=r"(r[2]), "=r"(r[3]) : "r"(addr) : "memory");
}
#define CP16(dst, src) asm volatile("cp.async.cg.shared.global [%0], [%1], 16;" :: "r"(dst), "l"(src) : "memory")
#define CP_COMMIT()    asm volatile("cp.async.commit_group;" ::: "memory")
#define CP_WAIT1()     asm volatile("cp.async.wait_group 1;" ::: "memory")

// ---- bulk async copy + mbarrier (sm_90 baseline PTX) ----
#define BULK(dst, srcptr, bytes, mbar) \
    asm volatile("cp.async.bulk.shared::cta.global.mbarrier::complete_tx::bytes [%0], [%1], %2, [%3];" \
        :: "r"(dst), "l"(srcptr), "r"(bytes), "r"(mbar) : "memory")
#define MBAR_INIT(a, c) asm volatile("mbarrier.init.shared.b64 [%0], %1;" :: "r"(a), "r"(c) : "memory")
#define MBAR_EXPECT_TX(a, tx) \
    asm volatile("mbarrier.arrive.expect_tx.shared.b64 _, [%0], %1;" :: "r"(a), "r"(tx) : "memory")
#define MBAR_WAIT(a, ph) do { \
    uint32_t _m = (a), _p = (ph), _d; \
    asm volatile("{\n\t.reg .pred p;\n\tmbarrier.try_wait.parity.acquire.cta.shared::cta.b64 p, [%1], %2;\n\tselp.b32 %0, 1, 0, p;\n\t}" \
        : "=r"(_d) : "r"(_m), "r"(_p) : "memory"); \
    if (!_d) { \
        asm volatile("{\n\t.reg .pred P1;\n\tWL_%=:\n\tmbarrier.try_wait.parity.acquire.cta.shared::cta.b64 P1, [%0], %1, 0x989680;\n\t@P1 bra.uni WD_%=;\n\tbra.uni WL_%=;\n\tWD_%=:\n\t}" \
            :: "r"(_m), "r"(_p) : "memory"); \
    } } while (0)

__device__ __forceinline__ uint32_t smem_u32(const void* p) {
    uint32_t a;
    asm("{ .reg .u64 t; cvta.to.shared.u64 t, %1; cvt.u32.u64 %0, t; }" : "=r"(a) : "l"(p));
    return a;
}
__device__ __forceinline__ float ex2(float x) {
    float y; asm("ex2.approx.f32 %0, %1;" : "=f"(y) : "f"(x)); return y;
}
__device__ __forceinline__ uint32_t hi2(float a, float b) {
    return ((uint32_t)__bfloat16_as_ushort(__float2bfloat16(b)) << 16) |
           (uint32_t)__bfloat16_as_ushort(__float2bfloat16(a));
}
__device__ __forceinline__ uint32_t lo2(float a, float b) {
    float ra = a - __bfloat162float(__float2bfloat16(a));
    float rb = b - __bfloat162float(__float2bfloat16(b));
    return hi2(ra, rb);
}

// ---------------------------------------------------------------------------
// Prep kernels (unchanged)
// ---------------------------------------------------------------------------
__global__ __launch_bounds__(256) void wprep_kernel(
    const float* __restrict__ Wq, const float* __restrict__ Wk,
    const float* __restrict__ Wv)
{
    int n = blockIdx.x;
    const float* W = (n < 64) ? Wq : (n < 128) ? Wk : Wv;
    int h = n & 63;
    for (int k = threadIdx.x; k < CC; k += 256) {
        float v = W[(size_t)k * HH + h];
        __nv_bfloat16 hi = __float2bfloat16(v);
        g_wt_hi[(size_t)n * CC + k] = hi;
        g_wt_lo[(size_t)n * CC + k] = __float2bfloat16(v - __bfloat162float(hi));
    }
}

__global__ __launch_bounds__(256) void xprep_kernel(const float* __restrict__ x)
{
    const int stride = gridDim.x * blockDim.x;
    for (int i = blockIdx.x * blockDim.x + threadIdx.x; i < BB*TT*CC/4; i += stride) {
        float4 v = *(const float4*)&x[(size_t)i * 4];
        uint2 hv, lv;
        hv.x = hi2(v.x, v.y);  hv.y = hi2(v.z, v.w);
        lv.x = lo2(v.x, v.y);  lv.y = lo2(v.z, v.w);
        *(uint2*)&g_xh[(size_t)i * 4] = hv;
        *(uint2*)&g_xl[(size_t)i * 4] = lv;
    }
}

// ---------------------------------------------------------------------------
// Projection GEMM (R11 main loop): 128 CTAs x 256 thr, M=128, N=192, K=32.
// Epilogue writes Q/K/V^T as blocked swizzled 64x64 tiles.
// ---------------------------------------------------------------------------
#define PROJ_SMEM 102400
#define PSS 25600

__global__ __launch_bounds__(256, 1) void proj_mma_kernel()
{
    extern __shared__ __nv_bfloat16 sb[];
    const uint32_t sbase = smem_u32(sb);

    const int tid  = threadIdx.x;
    const int wid  = tid >> 5;
    const int lane = tid & 31;
    const int g    = lane >> 2;
    const int tg   = lane & 3;
    const int m0   = blockIdx.x * 128;
    const int m0w  = (wid >> 1) * 32;
    const int n0w  = (wid & 1) * 96;

    const int m_off = (lane & 7) + ((lane >> 3) & 1) * 8;
    const int kA    = (lane >> 4) * 8;
    const int n_off = (lane & 7) + ((lane >> 4) & 1) * 8;
    const int kB    = ((lane >> 3) & 1) * 8;

    auto issue_chunk = [&](int kc, int s) {
        const int k0 = kc * 32;
        const uint32_t st = sbase + 2 * (s * PSS);
        #pragma unroll
        for (int t = 0; t < 4; t++) {
            int e = tid + t * 256;
            int arr = e >> 9;
            int ee  = e & 511;
            int row = ee >> 2, q = ee & 3;
            const __nv_bfloat16* src =
                (arr ? g_xl : g_xh) + (size_t)(m0 + row) * CC + k0 + q * 8;
            CP16(st + 2 * (arr * 5120 + row * 40 + q * 8), src);
        }
        #pragma unroll
        for (int t = 0; t < 6; t++) {
            int e = tid + t * 256;
            int arr = (e >= 768);
            int ee  = arr ? e - 768 : e;
            int row = ee >> 2, q = ee & 3;
            const __nv_bfloat16* src =
                (arr ? g_wt_lo : g_wt_hi) + (size_t)row * CC + k0 + q * 8;
            CP16(st + 2 * (10240 + arr * 7680 + row * 40 + q * 8), src);
        }
    };

    float acc[2][12][4];
    #pragma unroll
    for (int mt = 0; mt < 2; mt++)
        #pragma unroll
        for (int nt = 0; nt < 12; nt++)
            #pragma unroll
            for (int i = 0; i < 4; i++) acc[mt][nt][i] = 0.f;

    issue_chunk(0, 0); CP_COMMIT();
    issue_chunk(1, 1); CP_COMMIT();

    for (int kc = 0; kc < 32; kc++) {
        const int s = kc & 1;
        CP_WAIT1();
        __syncthreads();

        const uint32_t ah_b = sbase + 2 * (s * PSS);
        const uint32_t al_b = ah_b + 2 * 5120;
        const uint32_t bh_b = ah_b + 2 * 10240;
        const uint32_t bl_b = ah_b + 2 * 17920;

        #pragma unroll
        for (int ks = 0; ks < 32; ks += 16) {
            uint32_t ah[2][4], al[2][4];
            #pragma unroll
            for (int mt = 0; mt < 2; mt++) {
                int ro = (m0w + mt * 16 + m_off) * 40 + ks + kA;
                ldsm4(ah[mt], ah_b + 2 * ro);
                ldsm4(al[mt], al_b + 2 * ro);
            }
            #pragma unroll
            for (int p = 0; p < 6; p++) {
                int ro = (n0w + p * 16 + n_off) * 40 + ks + kB;
                uint32_t bh[4], bl[4];
                ldsm4(bh, bh_b + 2 * ro);
                ldsm4(bl, bl_b + 2 * ro);
                #pragma unroll
                for (int hf = 0; hf < 2; hf++) {
                    int nt = p * 2 + hf;
                    #pragma unroll
                    for (int mt = 0; mt < 2; mt++) {
                        mma16816(acc[mt][nt], ah[mt], bh + hf * 2);
                        mma16816(acc[mt][nt], ah[mt], bl + hf * 2);
                        mma16816(acc[mt][nt], al[mt], bh + hf * 2);
                    }
                }
            }
        }
        __syncthreads();
        if (kc + 2 < 32) issue_chunk(kc + 2, s);
        CP_COMMIT();
    }

    // ---- epilogue: blocked swizzled tiles ----
    const int b     = m0 >> 11;
    const int t0    = m0 & 2047;
    const int tile0 = b * 32 + (t0 >> 6);
    const float QSC = 0.125f * 1.44269504088896f;
    __nv_bfloat16* sTh = sb;               // [64 h][136] V^T staging (128 t)
    __nv_bfloat16* sTl = sb + 64 * 136;

    #pragma unroll
    for (int nt = 0; nt < 12; nt++) {
        int nbase = n0w + nt * 8;
        #pragma unroll
        for (int mt = 0; mt < 2; mt++) {
            int row = m0w + mt * 16 + g;       // 0..127 (row+8 never crosses a 64-tile)
            float c0 = acc[mt][nt][0], c1 = acc[mt][nt][1];
            float c2 = acc[mt][nt][2], c3 = acc[mt][nt][3];
            if (nbase < 128) {
                __nv_bfloat16* base;
                int col;
                if (nbase < 64) {
                    c0 *= QSC; c1 *= QSC; c2 *= QSC; c3 *= QSC;
                    base = g_qT; col = nbase + 2 * tg;
                } else {
                    base = g_kT; col = nbase - 64 + 2 * tg;
                }
                int tA = tile0 + (row >> 6);
                int r0 = row & 63;
                int r1 = r0 + 8;
                int u0 = r0 * 64 + ((((col >> 3) ^ (r0 & 7)) << 3)) + (col & 7);
                int u1 = r1 * 64 + ((((col >> 3) ^ (r1 & 7)) << 3)) + (col & 7);
                size_t tb = (size_t)(tA * 2) * 4096;
                *(uint32_t*)&base[tb + u0]        = hi2(c0, c1);
                *(uint32_t*)&base[tb + 4096 + u0] = lo2(c0, c1);
                *(uint32_t*)&base[tb + u1]        = hi2(c2, c3);
                *(uint32_t*)&base[tb + 4096 + u1] = lo2(c2, c3);
            } else {
                int h = nbase - 128 + 2 * tg;
                __nv_bfloat16 h0 = __float2bfloat16(c0), h1 = __float2bfloat16(c1);
                __nv_bfloat16 h2 = __float2bfloat16(c2), h3 = __float2bfloat16(c3);
                sTh[h * 136 + row]           = h0;
                sTh[(h + 1) * 136 + row]     = h1;
                sTh[h * 136 + row + 8]       = h2;
                sTh[(h + 1) * 136 + row + 8] = h3;
                sTl[h * 136 + row]           = __float2bfloat16(c0 - __bfloat162float(h0));
                sTl[(h + 1) * 136 + row]     = __float2bfloat16(c1 - __bfloat162float(h1));
                sTl[h * 136 + row + 8]       = __float2bfloat16(c2 - __bfloat162float(h2));
                sTl[(h + 1) * 136 + row + 8] = __float2bfloat16(c3 - __bfloat162float(h3));
            }
        }
    }
    __syncthreads();
    // V^T copy-out: 2 tiles (t halves), swizzled, 16B per thread-iter
    #pragma unroll
    for (int t = 0; t < 8; t++) {
        int e   = tid + t * 256;
        int arr = e >> 10;                 // hi / lo
        int ee  = e & 1023;
        int h   = ee >> 4;                 // 0..63
        int q   = ee & 15;                 // 16-byte group over 128 t
        int vt  = tile0 + (q >> 3);
        int tg8 = q & 7;
        int u   = h * 64 + ((tg8 ^ (h & 7)) << 3);
        uint4 v4 = *(const uint4*)&(arr ? sTl : sTh)[h * 136 + q * 8];
        *(uint4*)&g_vT[((size_t)(vt * 2 + arr)) * 4096 + u] = v4;
    }
}

// ---------------------------------------------------------------------------
// Attention: cp.async.bulk tile loads (4 bulk ops/stage from 1 thread),
// blocked swizzled global tiles, R11 job split (384 jobs, 304 CTAs).
// smem units: Qh@0 Ql@4096; stage s @8192+s*16384: Kh+0 Kl+4096 Vh+8192 Vl+12288
// total 40960 units = 81920 B
// ---------------------------------------------------------------------------
#define ATTN_CTAS 304
#define ATTN_JOBS 384
#define ATTN_SMEM 81920

__global__ __launch_bounds__(128, 1) void attn_mma_kernel(float* __restrict__ out)
{
    extern __shared__ __nv_bfloat16 sab[];
    const uint32_t sbase = smem_u32(sab);
    __shared__ __align__(8) unsigned long long smb[3];
    __shared__ int sJob;
    __shared__ int sLast;

    const uint32_t mbq  = smem_u32(&smb[0]);
    const uint32_t mbs0 = smem_u32(&smb[1]);
    const uint32_t mbs1 = smem_u32(&smb[2]);

    const int tid  = threadIdx.x;
    const int wid  = tid >> 5;
    const int lane = tid & 31;
    const int g    = lane >> 2;
    const int tg   = lane & 3;
    const int rw   = wid * 16;

    const int m_off = (lane & 7) + ((lane >> 3) & 1) * 8;
    const int kA8   = (lane >> 4);              // 0/1 : k 16B-unit offset for A frags
    const int n_off = (lane & 7) + ((lane >> 4) & 1) * 8;
    const int kB8   = ((lane >> 3) & 1);        // 0/1 : k 16B-unit offset for B frags

    const int qrow  = rw + m_off;
    const int qrx   = qrow & 7;

    for (;;) {
        if (tid == 0) sJob = atomicAdd(&g_ctr, 1);
        __syncthreads();
        const int job = sJob;
        if (job >= ATTN_JOBS) break;

        int qt, b, segid, seg0, segn, split;
        if (job < 256) {
            qt    = 31 - (job >> 4);
            b     = (job >> 1) & 7;
            segid = job & 1;
            split = 1;
            int total = qt + 1;
            int h = (total + 1) >> 1;
            if (segid == 0) { seg0 = 0; segn = h; }
            else            { seg0 = h; segn = total - h; }
        } else {
            int j2 = job - 256;
            qt = 15 - (j2 >> 3);
            b  = j2 & 7;
            segid = 0; split = 0; seg0 = 0; segn = qt + 1;
        }
        const int q0 = qt * 64;

        auto issue_kv = [&](int t, int s) {       // tid 0 only
            uint32_t mb = s ? mbs1 : mbs0;
            uint32_t st = sbase + 2 * (8192 + s * 16384);
            const __nv_bfloat16* kt = g_kT + ((size_t)(b * 32 + t) * 2) * 4096;
            const __nv_bfloat16* vt = g_vT + ((size_t)(b * 32 + t) * 2) * 4096;
            MBAR_EXPECT_TX(mb, 32768);
            BULK(st,             kt,        8192, mb);
            BULK(st + 2 * 4096,  kt + 4096, 8192, mb);
            BULK(st + 2 * 8192,  vt,        8192, mb);
            BULK(st + 2 * 12288, vt + 4096, 8192, mb);
        };

        if (tid == 0) {
            MBAR_INIT(mbq, 1);
            MBAR_INIT(mbs0, 1);
            MBAR_INIT(mbs1, 1);
        }
        __syncthreads();
        if (tid == 0) {
            const __nv_bfloat16* qtl = g_qT + ((size_t)(b * 32 + qt) * 2) * 4096;
            MBAR_EXPECT_TX(mbq, 16384);
            BULK(sbase,            qtl,        8192, mbq);
            BULK(sbase + 2 * 4096, qtl + 4096, 8192, mbq);
            issue_kv(seg0, 0);
            if (segn >= 2) issue_kv(seg0 + 1, 1);
        }

        // ---- wait Q, hoist fragments ----
        MBAR_WAIT(mbq, 0);
        uint32_t qfh[4][4], qfl[4][4];
        #pragma unroll
        for (int i = 0; i < 4; i++) {
            int u = qrow * 64 + (((2 * i + kA8) ^ qrx) << 3);
            ldsm4(qfh[i], sbase + 2 * u);
            ldsm4(qfl[i], sbase + 2 * (4096 + u));
        }

        int ph0 = 0, ph1 = 0;
        float m_i[2] = {-INFINITY, -INFINITY};
        float l_i[2] = {0.f, 0.f};
        float o[8][4];
        #pragma unroll
        for (int nt = 0; nt < 8; nt++)
            #pragma unroll
            for (int i = 0; i < 4; i++) o[nt][i] = 0.f;

        for (int tt = 0; tt < segn; tt++) {
            const int t = seg0 + tt;
            const int s = tt & 1;
            if (s) { MBAR_WAIT(mbs1, ph1); ph1 ^= 1; }
            else   { MBAR_WAIT(mbs0, ph0); ph0 ^= 1; }

            const uint32_t kh_b = sbase + 2 * (8192 + s * 16384);
            const uint32_t kl_b = kh_b + 2 * 4096;
            const uint32_t vh_b = kh_b + 2 * 8192;
            const uint32_t vl_b = kh_b + 2 * 12288;

            // ---- S = Q K^T ----
            float sc[8][4];
            #pragma unroll
            for (int nt = 0; nt < 8; nt++)
                #pragma unroll
                for (int i = 0; i < 4; i++) sc[nt][i] = 0.f;

            #pragma unroll
            for (int i = 0; i < 4; i++) {
                #pragma unroll
                for (int p = 0; p < 4; p++) {
                    int row = p * 16 + n_off;
                    int u = row * 64 + (((2 * i + kB8) ^ (row & 7)) << 3);
                    uint32_t bh[4], bl[4];
                    ldsm4(bh, kh_b + 2 * u);
                    ldsm4(bl, kl_b + 2 * u);
                    #pragma unroll
                    for (int hf = 0; hf < 2; hf++) {
                        int nt = p * 2 + hf;
                        mma16816(sc[nt], qfh[i], bh + hf * 2);
                        mma16816(sc[nt], qfh[i], bl + hf * 2);
                        mma16816(sc[nt], qfl[i], bh + hf * 2);
                    }
                }
            }

            if (t == qt) {   // diagonal chunk: causal mask
                int r0 = rw + g;
                #pragma unroll
                for (int nt = 0; nt < 8; nt++) {
                    int c0 = nt * 8 + 2 * tg;
                    if (c0     > r0)     sc[nt][0] = -INFINITY;
                    if (c0 + 1 > r0)     sc[nt][1] = -INFINITY;
                    if (c0     > r0 + 8) sc[nt][2] = -INFINITY;
                    if (c0 + 1 > r0 + 8) sc[nt][3] = -INFINITY;
                }
            }

            float mx0 = -INFINITY, mx1 = -INFINITY;
            #pragma unroll
            for (int nt = 0; nt < 8; nt++) {
                mx0 = fmaxf(mx0, fmaxf(sc[nt][0], sc[nt][1]));
                mx1 = fmaxf(mx1, fmaxf(sc[nt][2], sc[nt][3]));
            }
            mx0 = fmaxf(mx0, __shfl_xor_sync(0xffffffffu, mx0, 1));
            mx0 = fmaxf(mx0, __shfl_xor_sync(0xffffffffu, mx0, 2));
            mx1 = fmaxf(mx1, __shfl_xor_sync(0xffffffffu, mx1, 1));
            mx1 = fmaxf(mx1, __shfl_xor_sync(0xffffffffu, mx1, 2));

            float mn0 = fmaxf(m_i[0], mx0);
            float mn1 = fmaxf(m_i[1], mx1);
            float al0 = ex2(m_i[0] - mn0);
            float al1 = ex2(m_i[1] - mn1);
            m_i[0] = mn0;
            m_i[1] = mn1;
            #pragma unroll
            for (int nt = 0; nt < 8; nt++) {
                o[nt][0] *= al0; o[nt][1] *= al0;
                o[nt][2] *= al1; o[nt][3] *= al1;
            }

            float rs0 = 0.f, rs1 = 0.f;
            #pragma unroll
            for (int kk = 0; kk < 4; kk++) {
                int j0 = 2 * kk;
                float p00 = ex2(sc[j0][0] - mn0),     p01 = ex2(sc[j0][1] - mn0);
                float p02 = ex2(sc[j0][2] - mn1),     p03 = ex2(sc[j0][3] - mn1);
                float p10 = ex2(sc[j0 + 1][0] - mn0), p11 = ex2(sc[j0 + 1][1] - mn0);
                float p12 = ex2(sc[j0 + 1][2] - mn1), p13 = ex2(sc[j0 + 1][3] - mn1);
                rs0 += (p00 + p01) + (p10 + p11);
                rs1 += (p02 + p03) + (p12 + p13);
                uint32_t ph[4], pl[4];
                ph[0] = hi2(p00, p01);  pl[0] = lo2(p00, p01);
                ph[1] = hi2(p02, p03);  pl[1] = lo2(p02, p03);
                ph[2] = hi2(p10, p11);  pl[2] = lo2(p10, p11);
                ph[3] = hi2(p12, p13);  pl[3] = lo2(p12, p13);
                #pragma unroll
                for (int p = 0; p < 4; p++) {
                    int row = p * 16 + n_off;
                    int u = row * 64 + (((2 * kk + kB8) ^ (row & 7)) << 3);
                    uint32_t bvh[4], bvl[4];
                    ldsm4(bvh, vh_b + 2 * u);
                    ldsm4(bvl, vl_b + 2 * u);
                    #pragma unroll
                    for (int hf = 0; hf < 2; hf++) {
                        int nt = p * 2 + hf;
                        mma16816(o[nt], ph, bvh + hf * 2);
                        mma16816(o[nt], ph, bvl + hf * 2);
                        mma16816(o[nt], pl, bvh + hf * 2);
                    }
                }
            }
            rs0 += __shfl_xor_sync(0xffffffffu, rs0, 1);
            rs0 += __shfl_xor_sync(0xffffffffu, rs0, 2);
            rs1 += __shfl_xor_sync(0xffffffffu, rs1, 1);
            rs1 += __shfl_xor_sync(0xffffffffu, rs1, 2);
            l_i[0] = l_i[0] * al0 + rs0;
            l_i[1] = l_i[1] * al1 + rs1;

            __syncthreads();   // all readers done with stage s
            if (tid == 0 && tt + 2 < segn) issue_kv(seg0 + tt + 2, s);
        }

        // ---- epilogue ----
        if (!split) {
            float inv0 = 1.f / l_i[0];
            float inv1 = 1.f / l_i[1];
            int row0 = q0 + rw + g;
            #pragma unroll
            for (int nt = 0; nt < 8; nt++) {
                *(float2*)&out[((size_t)b * TT + row0) * HH + nt * 8 + 2 * tg] =
                    make_float2(o[nt][0] * inv0, o[nt][1] * inv0);
                *(float2*)&out[((size_t)b * TT + row0 + 8) * HH + nt * 8 + 2 * tg] =
                    make_float2(o[nt][2] * inv1, o[nt][3] * inv1);
            }
        } else {
            const int qi   = qt - 16;
            const int tile = b * 16 + qi;
            float* po = g_po + (size_t)(tile * 2 + segid) * 4096;
            float* pm = g_pm + (size_t)(tile * 2 + segid) * 64;
            float* pl = g_pl + (size_t)(tile * 2 + segid) * 64;
            int r0 = rw + g;
            #pragma unroll
            for (int nt = 0; nt < 8; nt++) {
                *(float2*)&po[r0 * 64 + nt * 8 + 2 * tg]       = make_float2(o[nt][0], o[nt][1]);
                *(float2*)&po[(r0 + 8) * 64 + nt * 8 + 2 * tg] = make_float2(o[nt][2], o[nt][3]);
            }
            if (tg == 0) {
                pm[r0] = m_i[0];  pl[r0] = l_i[0];
                pm[r0 + 8] = m_i[1];  pl[r0 + 8] = l_i[1];
            }
            __threadfence();
            __syncthreads();
            if (tid == 0) sLast = atomicAdd(&g_cnt[tile], 1);
            __syncthreads();
            if (sLast == 1) {
                __threadfence();
                const float* po0 = g_po + (size_t)(tile * 2 + 0) * 4096;
                const float* po1 = g_po + (size_t)(tile * 2 + 1) * 4096;
                const float* pm0 = g_pm + (size_t)(tile * 2 + 0) * 64;
                const float* pm1 = g_pm + (size_t)(tile * 2 + 1) * 64;
                const float* pl0 = g_pl + (size_t)(tile * 2 + 0) * 64;
                const float* pl1 = g_pl + (size_t)(tile * 2 + 1) * 64;
                int r  = tid >> 1;
                int c0 = (tid & 1) * 32;
                float m0v = pm0[r], m1v = pm1[r];
                float mm = fmaxf(m0v, m1v);
                float a0 = ex2(m0v - mm), a1 = ex2(m1v - mm);
                float inv = 1.f / (pl0[r] * a0 + pl1[r] * a1);
                float* dst = &out[((size_t)b * TT + q0 + r) * HH + c0];
                #pragma unroll 8
                for (int c = 0; c < 32; c++)
                    dst[c] = (po0[r * 64 + c0 + c] * a0 + po1[r * 64 + c0 + c] * a1) * inv;
                if (tid == 0) g_cnt[tile] = 0;
            }
        }
    }

    if (tid == 0) {
        if (atomicAdd(&g_done, 1) == ATTN_CTAS - 1) {
            g_ctr  = 0;
            g_done = 0;
        }
    }
}

extern "C" void kernel_launch(void* const* d_in, const int* in_sizes, int n_in,
                              void* d_out, int out_size)
{
    const float* x  = (const float*)d_in[0];
    const float* Wq = (const float*)d_in[1];
    const float* Wk = (const float*)d_in[2];
    const float* Wv = (const float*)d_in[3];
    float* out = (float*)d_out;

    cudaFuncSetAttribute(proj_mma_kernel,
                         cudaFuncAttributeMaxDynamicSharedMemorySize, PROJ_SMEM);
    cudaFuncSetAttribute(attn_mma_kernel,
                         cudaFuncAttributeMaxDynamicSharedMemorySize, ATTN_SMEM);

    wprep_kernel<<<192, 256>>>(Wq, Wk, Wv);
    xprep_kernel<<<2048, 256>>>(x);
    proj_mma_kernel<<<BB * TT / 128, 256, PROJ_SMEM>>>();
    attn_mma_kernel<<<ATTN_CTAS, 128, ATTN_SMEM>>>(out);
}

// round 15
// speedup vs baseline: 1.4238x; 1.1883x over previous
#include <cuda_runtime.h>
#include <cuda_bf16.h>
#include <math.h>
#include <cstdint>

#define BB 8
#define TT 2048
#define CC 1024
#define HH 64

// x as blocked swizzled 64x64 chunk-tiles: [(m64*16+kc)*2+hl][4096]
// unit(r,c) = r*64 + (((c>>3) ^ (r&7))<<3) + (c&7)
__device__ __nv_bfloat16 g_xT[256*16*2*4096];
// W^T chunk-tiles: [(kc*3+nsub)*2+hl][4096]   (n = mat*64+h rows, k cols)
__device__ __nv_bfloat16 g_wTt[16*3*2*4096];

// Q/K/V^T blocked swizzled 64x64 tiles: [(b*32+tile)*2+hl][4096]
__device__ __nv_bfloat16 g_qT[8*32*2*4096];   // [t-row][h-col], pre-scaled x0.125*log2e
__device__ __nv_bfloat16 g_kT[8*32*2*4096];
__device__ __nv_bfloat16 g_vT[8*32*2*4096];   // [h-row][t-col]

__device__ int g_ctr  = 0;
__device__ int g_done = 0;

// split-tile partials (qt>=16, 2 segments)
__device__ float g_po[8*16*2*64*64];
__device__ float g_pm[8*16*2*64];
__device__ float g_pl[8*16*2*64];
__device__ int   g_cnt[8*16];

// ---- mma.sync m16n8k16 bf16 (sm_80 baseline) ----
__device__ __forceinline__ void mma16816(float* c, const uint32_t* a, const uint32_t* b) {
    asm volatile(
        "mma.sync.aligned.m16n8k16.row.col.f32.bf16.bf16.f32 "
        "{%0,%1,%2,%3}, {%4,%5,%6,%7}, {%8,%9}, {%0,%1,%2,%3};"
        : "+f"(c[0]), "+f"(c[1]), "+f"(c[2]), "+f"(c[3])
        : "r"(a[0]), "r"(a[1]), "r"(a[2]), "r"(a[3]), "r"(b[0]), "r"(b[1]));
}
__device__ __forceinline__ void ldsm4(uint32_t* r, uint32_t addr) {
    asm volatile("ldmatrix.sync.aligned.m8n8.x4.shared.b16 {%0,%1,%2,%3}, [%4];"
        : "=r"(r[0]), "=r"(r[1]), "=r"(r[2]), "=r"(r[3]) : "r"(addr) : "memory");
}

// ---- bulk async copy + mbarrier (sm_90 baseline PTX) ----
#define BULK(dst, srcptr, bytes, mbar) \
    asm volatile("cp.async.bulk.shared::cta.global.mbarrier::complete_tx::bytes [%0], [%1], %2, [%3];" \
        :: "r"(dst), "l"(srcptr), "r"(bytes), "r"(mbar) : "memory")
#define MBAR_INIT(a, c) asm volatile("mbarrier.init.shared.b64 [%0], %1;" :: "r"(a), "r"(c) : "memory")
#define MBAR_EXPECT_TX(a, tx) \
    asm volatile("mbarrier.arrive.expect_tx.shared.b64 _, [%0], %1;" :: "r"(a), "r"(tx) : "memory")
#define MBAR_WAIT(a, ph) do { \
    uint32_t _m = (a), _p = (ph), _d; \
    asm volatile("{\n\t.reg .pred p;\n\tmbarrier.try_wait.parity.acquire.cta.shared::cta.b64 p, [%1], %2;\n\tselp.b32 %0, 1, 0, p;\n\t}" \
        : "=r"(_d) : "r"(_m), "r"(_p) : "memory"); \
    if (!_d) { \
        asm volatile("{\n\t.reg .pred P1;\n\tWL_%=:\n\tmbarrier.try_wait.parity.acquire.cta.shared::cta.b64 P1, [%0], %1, 0x989680;\n\t@P1 bra.uni WD_%=;\n\tbra.uni WL_%=;\n\tWD_%=:\n\t}" \
            :: "r"(_m), "r"(_p) : "memory"); \
    } } while (0)

__device__ __forceinline__ uint32_t smem_u32(const void* p) {
    uint32_t a;
    asm("{ .reg .u64 t; cvta.to.shared.u64 t, %1; cvt.u32.u64 %0, t; }" : "=r"(a) : "l"(p));
    return a;
}
__device__ __forceinline__ float ex2(float x) {
    float y; asm("ex2.approx.f32 %0, %1;" : "=f"(y) : "f"(x)); return y;
}
__device__ __forceinline__ uint32_t hi2(float a, float b) {
    return ((uint32_t)__bfloat16_as_ushort(__float2bfloat16(b)) << 16) |
           (uint32_t)__bfloat16_as_ushort(__float2bfloat16(a));
}
__device__ __forceinline__ uint32_t lo2(float a, float b) {
    float ra = a - __bfloat162float(__float2bfloat16(a));
    float rb = b - __bfloat162float(__float2bfloat16(b));
    return hi2(ra, rb);
}

// ---------------------------------------------------------------------------
// Prep kernels: write x / W^T as swizzled chunk-tiles (bulk-copy sources)
// ---------------------------------------------------------------------------
__global__ __launch_bounds__(256) void wprep_kernel(
    const float* __restrict__ Wq, const float* __restrict__ Wk,
    const float* __restrict__ Wv)
{
    // 24576 (n, k-group) pairs; grid 96 x 256
    int idx = blockIdx.x * 256 + threadIdx.x;
    int n  = idx >> 7;             // 0..191
    int gq = idx & 127;            // k group of 8
    int k0 = gq * 8;
    const float* W = (n < 64) ? Wq : (n < 128) ? Wk : Wv;
    int h = n & 63;
    int nsub = n >> 6, r = n & 63;
    int kc = k0 >> 6, ccg = (k0 & 63) >> 3;
    int u = r * 64 + (((ccg) ^ (r & 7)) << 3);
    size_t tb = ((size_t)(kc * 3 + nsub) * 2) * 4096;
    uint32_t hv[4], lv[4];
    #pragma unroll
    for (int i = 0; i < 4; i++) {
        float a = W[(size_t)(k0 + 2 * i) * HH + h];
        float c = W[(size_t)(k0 + 2 * i + 1) * HH + h];
        hv[i] = hi2(a, c);
        lv[i] = lo2(a, c);
    }
    *(uint4*)&g_wTt[tb + u]        = *(uint4*)hv;
    *(uint4*)&g_wTt[tb + 4096 + u] = *(uint4*)lv;
}

__global__ __launch_bounds__(256) void xprep_kernel(const float* __restrict__ x)
{
    // 2M (row, k-group) pairs
    const int stride = gridDim.x * blockDim.x;
    for (int idx = blockIdx.x * 256 + threadIdx.x; idx < BB*TT*CC/8; idx += stride) {
        int m  = idx >> 7;
        int k0 = (idx & 127) * 8;
        float4 v0 = *(const float4*)&x[(size_t)m * CC + k0];
        float4 v1 = *(const float4*)&x[(size_t)m * CC + k0 + 4];
        uint32_t hv[4], lv[4];
        hv[0] = hi2(v0.x, v0.y);  lv[0] = lo2(v0.x, v0.y);
        hv[1] = hi2(v0.z, v0.w);  lv[1] = lo2(v0.z, v0.w);
        hv[2] = hi2(v1.x, v1.y);  lv[2] = lo2(v1.x, v1.y);
        hv[3] = hi2(v1.z, v1.w);  lv[3] = lo2(v1.z, v1.w);
        int m64 = m >> 6, r = m & 63;
        int kc = k0 >> 6, ccg = (k0 & 63) >> 3;
        int u = r * 64 + ((ccg ^ (r & 7)) << 3);
        size_t tb = ((size_t)(m64 * 16 + kc) * 2) * 4096;
        *(uint4*)&g_xT[tb + u]        = *(uint4*)hv;
        *(uint4*)&g_xT[tb + 4096 + u] = *(uint4*)lv;
    }
}

// ---------------------------------------------------------------------------
// Projection GEMM: bulk-copy loads.  128 CTAs x 256 thr (8 warps 4Mx2N),
// M=128, N=192, K chunks of 64 (16 chunks), double-buffered.
// smem units per stage (@ s*40960): A[sub 2][hl 2] @0..16384 (4 x 4096)
//                                   B[sub 3][hl 2] @16384..40960 (6 x 4096)
// 2 stages = 81920 units = 163840 B (1 CTA/SM).
// ---------------------------------------------------------------------------
#define PROJ_SMEM 163840

__global__ __launch_bounds__(256, 1) void proj_mma_kernel()
{
    extern __shared__ __nv_bfloat16 sb[];
    const uint32_t sbase = smem_u32(sb);
    __shared__ __align__(8) unsigned long long smb[2];
    const uint32_t mb0 = smem_u32(&smb[0]);
    const uint32_t mb1 = smem_u32(&smb[1]);

    const int tid  = threadIdx.x;
    const int wid  = tid >> 5;
    const int lane = tid & 31;
    const int g    = lane >> 2;
    const int tg   = lane & 3;
    const int m0   = blockIdx.x * 128;
    const int m64b = blockIdx.x * 2;       // first m64 tile index
    const int m0w  = (wid >> 1) * 32;
    const int n0w  = (wid & 1) * 96;

    const int m_off = (lane & 7) + ((lane >> 3) & 1) * 8;
    const int kA8   = (lane >> 4);
    const int n_off = (lane & 7) + ((lane >> 4) & 1) * 8;
    const int kB8   = ((lane >> 3) & 1);

    auto issue_chunk = [&](int kc, int s) {   // tid 0 only
        uint32_t mb = s ? mb1 : mb0;
        uint32_t st = sbase + 2 * (s * 40960);
        MBAR_EXPECT_TX(mb, 81920);
        #pragma unroll
        for (int sub = 0; sub < 2; sub++) {
            const __nv_bfloat16* src = g_xT + ((size_t)((m64b + sub) * 16 + kc) * 2) * 4096;
            BULK(st + 2 * (sub * 8192),        src,        8192, mb);
            BULK(st + 2 * (sub * 8192 + 4096), src + 4096, 8192, mb);
        }
        #pragma unroll
        for (int sub = 0; sub < 3; sub++) {
            const __nv_bfloat16* src = g_wTt + ((size_t)(kc * 3 + sub) * 2) * 4096;
            BULK(st + 2 * (16384 + sub * 8192),        src,        8192, mb);
            BULK(st + 2 * (16384 + sub * 8192 + 4096), src + 4096, 8192, mb);
        }
    };

    if (tid == 0) {
        MBAR_INIT(mb0, 1);
        MBAR_INIT(mb1, 1);
    }
    __syncthreads();
    if (tid == 0) {
        issue_chunk(0, 0);
        issue_chunk(1, 1);
    }

    float acc[2][12][4];
    #pragma unroll
    for (int mt = 0; mt < 2; mt++)
        #pragma unroll
        for (int nt = 0; nt < 12; nt++)
            #pragma unroll
            for (int i = 0; i < 4; i++) acc[mt][nt][i] = 0.f;

    int ph0 = 0, ph1 = 0;
    for (int kc = 0; kc < 16; kc++) {
        const int s = kc & 1;
        if (s) { MBAR_WAIT(mb1, ph1); ph1 ^= 1; }
        else   { MBAR_WAIT(mb0, ph0); ph0 ^= 1; }

        const uint32_t st = sbase + 2 * (s * 40960);

        #pragma unroll
        for (int i = 0; i < 4; i++) {        // 4 k-steps of 16 within the 64-chunk
            uint32_t ah[2][4], al[2][4];
            #pragma unroll
            for (int mt = 0; mt < 2; mt++) {
                int row = m0w + mt * 16 + m_off;     // 0..127
                int sub = row >> 6, r = row & 63;
                int u = r * 64 + (((2 * i + kA8) ^ (r & 7)) << 3);
                ldsm4(ah[mt], st + 2 * (sub * 8192 + u));
                ldsm4(al[mt], st + 2 * (sub * 8192 + 4096 + u));
            }
            #pragma unroll
            for (int p = 0; p < 6; p++) {
                int row = n0w + p * 16 + n_off;      // 0..191
                int sub = row >> 6, r = row & 63;
                int u = r * 64 + (((2 * i + kB8) ^ (r & 7)) << 3);
                uint32_t bh[4], bl[4];
                ldsm4(bh, st + 2 * (16384 + sub * 8192 + u));
                ldsm4(bl, st + 2 * (16384 + sub * 8192 + 4096 + u));
                #pragma unroll
                for (int hf = 0; hf < 2; hf++) {
                    int nt = p * 2 + hf;
                    #pragma unroll
                    for (int mt = 0; mt < 2; mt++) {
                        mma16816(acc[mt][nt], ah[mt], bh + hf * 2);
                        mma16816(acc[mt][nt], ah[mt], bl + hf * 2);
                        mma16816(acc[mt][nt], al[mt], bh + hf * 2);
                    }
                }
            }
        }
        __syncthreads();                     // all readers done with stage s
        if (tid == 0 && kc + 2 < 16) issue_chunk(kc + 2, s);
    }

    // ---- epilogue: blocked swizzled tiles (same as R14) ----
    const int b     = m0 >> 11;
    const int t0    = m0 & 2047;
    const int tile0 = b * 32 + (t0 >> 6);
    const float QSC = 0.125f * 1.44269504088896f;
    __nv_bfloat16* sTh = sb;               // [64 h][136] V^T staging (128 t)
    __nv_bfloat16* sTl = sb + 64 * 136;

    #pragma unroll
    for (int nt = 0; nt < 12; nt++) {
        int nbase = n0w + nt * 8;
        #pragma unroll
        for (int mt = 0; mt < 2; mt++) {
            int row = m0w + mt * 16 + g;
            float c0 = acc[mt][nt][0], c1 = acc[mt][nt][1];
            float c2 = acc[mt][nt][2], c3 = acc[mt][nt][3];
            if (nbase < 128) {
                __nv_bfloat16* base;
                int col;
                if (nbase < 64) {
                    c0 *= QSC; c1 *= QSC; c2 *= QSC; c3 *= QSC;
                    base = g_qT; col = nbase + 2 * tg;
                } else {
                    base = g_kT; col = nbase - 64 + 2 * tg;
                }
                int tA = tile0 + (row >> 6);
                int r0 = row & 63;
                int r1 = r0 + 8;
                int u0 = r0 * 64 + ((((col >> 3) ^ (r0 & 7)) << 3)) + (col & 7);
                int u1 = r1 * 64 + ((((col >> 3) ^ (r1 & 7)) << 3)) + (col & 7);
                size_t tb = (size_t)(tA * 2) * 4096;
                *(uint32_t*)&base[tb + u0]        = hi2(c0, c1);
                *(uint32_t*)&base[tb + 4096 + u0] = lo2(c0, c1);
                *(uint32_t*)&base[tb + u1]        = hi2(c2, c3);
                *(uint32_t*)&base[tb + 4096 + u1] = lo2(c2, c3);
            } else {
                int h = nbase - 128 + 2 * tg;
                __nv_bfloat16 h0 = __float2bfloat16(c0), h1 = __float2bfloat16(c1);
                __nv_bfloat16 h2 = __float2bfloat16(c2), h3 = __float2bfloat16(c3);
                sTh[h * 136 + row]           = h0;
                sTh[(h + 1) * 136 + row]     = h1;
                sTh[h * 136 + row + 8]       = h2;
                sTh[(h + 1) * 136 + row + 8] = h3;
                sTl[h * 136 + row]           = __float2bfloat16(c0 - __bfloat162float(h0));
                sTl[(h + 1) * 136 + row]     = __float2bfloat16(c1 - __bfloat162float(h1));
                sTl[h * 136 + row + 8]       = __float2bfloat16(c2 - __bfloat162float(h2));
                sTl[(h + 1) * 136 + row + 8] = __float2bfloat16(c3 - __bfloat162float(h3));
            }
        }
    }
    __syncthreads();
    #pragma unroll
    for (int t = 0; t < 8; t++) {
        int e   = tid + t * 256;
        int arr = e >> 10;
        int ee  = e & 1023;
        int h   = ee >> 4;
        int q   = ee & 15;
        int vt  = tile0 + (q >> 3);
        int tg8 = q & 7;
        int u   = h * 64 + ((tg8 ^ (h & 7)) << 3);
        uint4 v4 = *(const uint4*)&(arr ? sTl : sTh)[h * 136 + q * 8];
        *(uint4*)&g_vT[((size_t)(vt * 2 + arr)) * 4096 + u] = v4;
    }
}

// ---------------------------------------------------------------------------
// Attention (R14 verbatim): bulk tile loads, 384 jobs, 304 CTAs.
// smem units: Qh@0 Ql@4096; stage s @8192+s*16384: Kh+0 Kl+4096 Vh+8192 Vl+12288
// ---------------------------------------------------------------------------
#define ATTN_CTAS 304
#define ATTN_JOBS 384
#define ATTN_SMEM 81920

__global__ __launch_bounds__(128, 1) void attn_mma_kernel(float* __restrict__ out)
{
    extern __shared__ __nv_bfloat16 sab[];
    const uint32_t sbase = smem_u32(sab);
    __shared__ __align__(8) unsigned long long smb[3];
    __shared__ int sJob;
    __shared__ int sLast;

    const uint32_t mbq  = smem_u32(&smb[0]);
    const uint32_t mbs0 = smem_u32(&smb[1]);
    const uint32_t mbs1 = smem_u32(&smb[2]);

    const int tid  = threadIdx.x;
    const int wid  = tid >> 5;
    const int lane = tid & 31;
    const int g    = lane >> 2;
    const int tg   = lane & 3;
    const int rw   = wid * 16;

    const int m_off = (lane & 7) + ((lane >> 3) & 1) * 8;
    const int kA8   = (lane >> 4);
    const int n_off = (lane & 7) + ((lane >> 4) & 1) * 8;
    const int kB8   = ((lane >> 3) & 1);

    const int qrow  = rw + m_off;
    const int qrx   = qrow & 7;

    for (;;) {
        if (tid == 0) sJob = atomicAdd(&g_ctr, 1);
        __syncthreads();
        const int job = sJob;
        if (job >= ATTN_JOBS) break;

        int qt, b, segid, seg0, segn, split;
        if (job < 256) {
            qt    = 31 - (job >> 4);
            b     = (job >> 1) & 7;
            segid = job & 1;
            split = 1;
            int total = qt + 1;
            int h = (total + 1) >> 1;
            if (segid == 0) { seg0 = 0; segn = h; }
            else            { seg0 = h; segn = total - h; }
        } else {
            int j2 = job - 256;
            qt = 15 - (j2 >> 3);
            b  = j2 & 7;
            segid = 0; split = 0; seg0 = 0; segn = qt + 1;
        }
        const int q0 = qt * 64;

        auto issue_kv = [&](int t, int s) {
            uint32_t mb = s ? mbs1 : mbs0;
            uint32_t st = sbase + 2 * (8192 + s * 16384);
            const __nv_bfloat16* kt = g_kT + ((size_t)(b * 32 + t) * 2) * 4096;
            const __nv_bfloat16* vt = g_vT + ((size_t)(b * 32 + t) * 2) * 4096;
            MBAR_EXPECT_TX(mb, 32768);
            BULK(st,             kt,        8192, mb);
            BULK(st + 2 * 4096,  kt + 4096, 8192, mb);
            BULK(st + 2 * 8192,  vt,        8192, mb);
            BULK(st + 2 * 12288, vt + 4096, 8192, mb);
        };

        if (tid == 0) {
            MBAR_INIT(mbq, 1);
            MBAR_INIT(mbs0, 1);
            MBAR_INIT(mbs1, 1);
        }
        __syncthreads();
        if (tid == 0) {
            const __nv_bfloat16* qtl = g_qT + ((size_t)(b * 32 + qt) * 2) * 4096;
            MBAR_EXPECT_TX(mbq, 16384);
            BULK(sbase,            qtl,        8192, mbq);
            BULK(sbase + 2 * 4096, qtl + 4096, 8192, mbq);
            issue_kv(seg0, 0);
            if (segn >= 2) issue_kv(seg0 + 1, 1);
        }

        MBAR_WAIT(mbq, 0);
        uint32_t qfh[4][4], qfl[4][4];
        #pragma unroll
        for (int i = 0; i < 4; i++) {
            int u = qrow * 64 + (((2 * i + kA8) ^ qrx) << 3);
            ldsm4(qfh[i], sbase + 2 * u);
            ldsm4(qfl[i], sbase + 2 * (4096 + u));
        }

        int ph0 = 0, ph1 = 0;
        float m_i[2] = {-INFINITY, -INFINITY};
        float l_i[2] = {0.f, 0.f};
        float o[8][4];
        #pragma unroll
        for (int nt = 0; nt < 8; nt++)
            #pragma unroll
            for (int i = 0; i < 4; i++) o[nt][i] = 0.f;

        for (int tt = 0; tt < segn; tt++) {
            const int t = seg0 + tt;
            const int s = tt & 1;
            if (s) { MBAR_WAIT(mbs1, ph1); ph1 ^= 1; }
            else   { MBAR_WAIT(mbs0, ph0); ph0 ^= 1; }

            const uint32_t kh_b = sbase + 2 * (8192 + s * 16384);
            const uint32_t kl_b = kh_b + 2 * 4096;
            const uint32_t vh_b = kh_b + 2 * 8192;
            const uint32_t vl_b = kh_b + 2 * 12288;

            float sc[8][4];
            #pragma unroll
            for (int nt = 0; nt < 8; nt++)
                #pragma unroll
                for (int i = 0; i < 4; i++) sc[nt][i] = 0.f;

            #pragma unroll
            for (int i = 0; i < 4; i++) {
                #pragma unroll
                for (int p = 0; p < 4; p++) {
                    int row = p * 16 + n_off;
                    int u = row * 64 + (((2 * i + kB8) ^ (row & 7)) << 3);
                    uint32_t bh[4], bl[4];
                    ldsm4(bh, kh_b + 2 * u);
                    ldsm4(bl, kl_b + 2 * u);
                    #pragma unroll
                    for (int hf = 0; hf < 2; hf++) {
                        int nt = p * 2 + hf;
                        mma16816(sc[nt], qfh[i], bh + hf * 2);
                        mma16816(sc[nt], qfh[i], bl + hf * 2);
                        mma16816(sc[nt], qfl[i], bh + hf * 2);
                    }
                }
            }

            if (t == qt) {
                int r0 = rw + g;
                #pragma unroll
                for (int nt = 0; nt < 8; nt++) {
                    int c0 = nt * 8 + 2 * tg;
                    if (c0     > r0)     sc[nt][0] = -INFINITY;
                    if (c0 + 1 > r0)     sc[nt][1] = -INFINITY;
                    if (c0     > r0 + 8) sc[nt][2] = -INFINITY;
                    if (c0 + 1 > r0 + 8) sc[nt][3] = -INFINITY;
                }
            }

            float mx0 = -INFINITY, mx1 = -INFINITY;
            #pragma unroll
            for (int nt = 0; nt < 8; nt++) {
                mx0 = fmaxf(mx0, fmaxf(sc[nt][0], sc[nt][1]));
                mx1 = fmaxf(mx1, fmaxf(sc[nt][2], sc[nt][3]));
            }
            mx0 = fmaxf(mx0, __shfl_xor_sync(0xffffffffu, mx0, 1));
            mx0 = fmaxf(mx0, __shfl_xor_sync(0xffffffffu, mx0, 2));
            mx1 = fmaxf(mx1, __shfl_xor_sync(0xffffffffu, mx1, 1));
            mx1 = fmaxf(mx1, __shfl_xor_sync(0xffffffffu, mx1, 2));

            float mn0 = fmaxf(m_i[0], mx0);
            float mn1 = fmaxf(m_i[1], mx1);
            float al0 = ex2(m_i[0] - mn0);
            float al1 = ex2(m_i[1] - mn1);
            m_i[0] = mn0;
            m_i[1] = mn1;
            #pragma unroll
            for (int nt = 0; nt < 8; nt++) {
                o[nt][0] *= al0; o[nt][1] *= al0;
                o[nt][2] *= al1; o[nt][3] *= al1;
            }

            float rs0 = 0.f, rs1 = 0.f;
            #pragma unroll
            for (int kk = 0; kk < 4; kk++) {
                int j0 = 2 * kk;
                float p00 = ex2(sc[j0][0] - mn0),     p01 = ex2(sc[j0][1] - mn0);
                float p02 = ex2(sc[j0][2] - mn1),     p03 = ex2(sc[j0][3] - mn1);
                float p10 = ex2(sc[j0 + 1][0] - mn0), p11 = ex2(sc[j0 + 1][1] - mn0);
                float p12 = ex2(sc[j0 + 1][2] - mn1), p13 = ex2(sc[j0 + 1][3] - mn1);
                rs0 += (p00 + p01) + (p10 + p11);
                rs1 += (p02 + p03) + (p12 + p13);
                uint32_t ph[4], pl[4];
                ph[0] = hi2(p00, p01);  pl[0] = lo2(p00, p01);
                ph[1] = hi2(p02, p03);  pl[1] = lo2(p02, p03);
                ph[2] = hi2(p10, p11);  pl[2] = lo2(p10, p11);
                ph[3] = hi2(p12, p13);  pl[3] = lo2(p12, p13);
                #pragma unroll
                for (int p = 0; p < 4; p++) {
                    int row = p * 16 + n_off;
                    int u = row * 64 + (((2 * kk + kB8) ^ (row & 7)) << 3);
                    uint32_t bvh[4], bvl[4];
                    ldsm4(bvh, vh_b + 2 * u);
                    ldsm4(bvl, vl_b + 2 * u);
                    #pragma unroll
                    for (int hf = 0; hf < 2; hf++) {
                        int nt = p * 2 + hf;
                        mma16816(o[nt], ph, bvh + hf * 2);
                        mma16816(o[nt], ph, bvl + hf * 2);
                        mma16816(o[nt], pl, bvh + hf * 2);
                    }
                }
            }
            rs0 += __shfl_xor_sync(0xffffffffu, rs0, 1);
            rs0 += __shfl_xor_sync(0xffffffffu, rs0, 2);
            rs1 += __shfl_xor_sync(0xffffffffu, rs1, 1);
            rs1 += __shfl_xor_sync(0xffffffffu, rs1, 2);
            l_i[0] = l_i[0] * al0 + rs0;
            l_i[1] = l_i[1] * al1 + rs1;

            __syncthreads();
            if (tid == 0 && tt + 2 < segn) issue_kv(seg0 + tt + 2, s);
        }

        if (!split) {
            float inv0 = 1.f / l_i[0];
            float inv1 = 1.f / l_i[1];
            int row0 = q0 + rw + g;
            #pragma unroll
            for (int nt = 0; nt < 8; nt++) {
                *(float2*)&out[((size_t)b * TT + row0) * HH + nt * 8 + 2 * tg] =
                    make_float2(o[nt][0] * inv0, o[nt][1] * inv0);
                *(float2*)&out[((size_t)b * TT + row0 + 8) * HH + nt * 8 + 2 * tg] =
                    make_float2(o[nt][2] * inv1, o[nt][3] * inv1);
            }
        } else {
            const int qi   = qt - 16;
            const int tile = b * 16 + qi;
            float* po = g_po + (size_t)(tile * 2 + segid) * 4096;
            float* pm = g_pm + (size_t)(tile * 2 + segid) * 64;
            float* pl = g_pl + (size_t)(tile * 2 + segid) * 64;
            int r0 = rw + g;
            #pragma unroll
            for (int nt = 0; nt < 8; nt++) {
                *(float2*)&po[r0 * 64 + nt * 8 + 2 * tg]       = make_float2(o[nt][0], o[nt][1]);
                *(float2*)&po[(r0 + 8) * 64 + nt * 8 + 2 * tg] = make_float2(o[nt][2], o[nt][3]);
            }
            if (tg == 0) {
                pm[r0] = m_i[0];  pl[r0] = l_i[0];
                pm[r0 + 8] = m_i[1];  pl[r0 + 8] = l_i[1];
            }
            __threadfence();
            __syncthreads();
            if (tid == 0) sLast = atomicAdd(&g_cnt[tile], 1);
            __syncthreads();
            if (sLast == 1) {
                __threadfence();
                const float* po0 = g_po + (size_t)(tile * 2 + 0) * 4096;
                const float* po1 = g_po + (size_t)(tile * 2 + 1) * 4096;
                const float* pm0 = g_pm + (size_t)(tile * 2 + 0) * 64;
                const float* pm1 = g_pm + (size_t)(tile * 2 + 1) * 64;
                const float* pl0 = g_pl + (size_t)(tile * 2 + 0) * 64;
                const float* pl1 = g_pl + (size_t)(tile * 2 + 1) * 64;
                int r  = tid >> 1;
                int c0 = (tid & 1) * 32;
                float m0v = pm0[r], m1v = pm1[r];
                float mm = fmaxf(m0v, m1v);
                float a0 = ex2(m0v - mm), a1 = ex2(m1v - mm);
                float inv = 1.f / (pl0[r] * a0 + pl1[r] * a1);
                float* dst = &out[((size_t)b * TT + q0 + r) * HH + c0];
                #pragma unroll 8
                for (int c = 0; c < 32; c++)
                    dst[c] = (po0[r * 64 + c0 + c] * a0 + po1[r * 64 + c0 + c] * a1) * inv;
                if (tid == 0) g_cnt[tile] = 0;
            }
        }
    }

    if (tid == 0) {
        if (atomicAdd(&g_done, 1) == ATTN_CTAS - 1) {
            g_ctr  = 0;
            g_done = 0;
        }
    }
}

extern "C" void kernel_launch(void* const* d_in, const int* in_sizes, int n_in,
                              void* d_out, int out_size)
{
    const float* x  = (const float*)d_in[0];
    const float* Wq = (const float*)d_in[1];
    const float* Wk = (const float*)d_in[2];
    const float* Wv = (const float*)d_in[3];
    float* out = (float*)d_out;

    cudaFuncSetAttribute(proj_mma_kernel,
                         cudaFuncAttributeMaxDynamicSharedMemorySize, PROJ_SMEM);
    cudaFuncSetAttribute(attn_mma_kernel,
                         cudaFuncAttributeMaxDynamicSharedMemorySize, ATTN_SMEM);

    wprep_kernel<<<96, 256>>>(Wq, Wk, Wv);
    xprep_kernel<<<2048, 256>>>(x);
    proj_mma_kernel<<<BB * TT / 128, 256, PROJ_SMEM>>>();
    attn_mma_kernel<<<ATTN_CTAS, 128, ATTN_SMEM>>>(out);
}